// round 1
// baseline (speedup 1.0000x reference)
#include <cuda_runtime.h>
#include <cstddef>

#define T_LEN 2048
#define BSZ   4
#define EMB   1024
#define NH    16
#define HDIM  64
#define MROWS (T_LEN * BSZ)   // 8192
#define BH    (BSZ * NH)      // 64

// ---------------------------------------------------------------------------
// Scratch (device globals; allocation inside kernel_launch is forbidden)
// ---------------------------------------------------------------------------
__device__ float g_q[(size_t)BH * T_LEN * HDIM];     // [B,H,T,HD]  33.5 MB
__device__ float g_k[(size_t)BH * T_LEN * HDIM];
__device__ float g_v[(size_t)BH * T_LEN * HDIM];
__device__ float g_ctx[(size_t)MROWS * EMB];         // [T,B,E]     33.5 MB
__device__ float g_S[(size_t)BH * T_LEN * T_LEN];    // [B,H,Tq,Tk]  1 GiB

// ---------------------------------------------------------------------------
// NT GEMM: C = A[M,K] * W[N,K]^T (+bias)*scale, K = EMB = 1024
// BM=BN=128, BK=8, 256 threads, 8x8 microtile
// mode 0: write to [B,H,T,HD] layout (for q/k/v), mode 1: plain [M,E]
// ---------------------------------------------------------------------------
__global__ __launch_bounds__(256) void sgemm_nt(
    const float* __restrict__ A,
    const float* __restrict__ W,
    const float* __restrict__ bias,
    float* __restrict__ C,
    float scale, int mode)
{
    const int K = EMB;
    __shared__ float As[8][132];
    __shared__ float Ws[8][132];

    const int tid = threadIdx.x;
    const int m0  = blockIdx.y * 128;
    const int n0  = blockIdx.x * 128;
    const int lr  = tid >> 1;          // 0..127
    const int lc  = (tid & 1) * 4;     // 0 or 4
    const int ty  = tid >> 4;          // 0..15
    const int tx  = tid & 15;          // 0..15

    const float* Aptr = A + (size_t)(m0 + lr) * K + lc;
    const float* Wptr = W + (size_t)(n0 + lr) * K + lc;

    float acc[8][8];
#pragma unroll
    for (int i = 0; i < 8; i++)
#pragma unroll
        for (int j = 0; j < 8; j++) acc[i][j] = 0.0f;

    for (int k0 = 0; k0 < K; k0 += 8) {
        float4 a4 = *(const float4*)(Aptr + k0);
        float4 w4 = *(const float4*)(Wptr + k0);
        As[lc + 0][lr] = a4.x; As[lc + 1][lr] = a4.y;
        As[lc + 2][lr] = a4.z; As[lc + 3][lr] = a4.w;
        Ws[lc + 0][lr] = w4.x; Ws[lc + 1][lr] = w4.y;
        Ws[lc + 2][lr] = w4.z; Ws[lc + 3][lr] = w4.w;
        __syncthreads();
#pragma unroll
        for (int kk = 0; kk < 8; kk++) {
            float4 af0 = *(const float4*)&As[kk][ty * 8];
            float4 af1 = *(const float4*)&As[kk][ty * 8 + 4];
            float4 bf0 = *(const float4*)&Ws[kk][tx * 8];
            float4 bf1 = *(const float4*)&Ws[kk][tx * 8 + 4];
            float a[8] = {af0.x, af0.y, af0.z, af0.w, af1.x, af1.y, af1.z, af1.w};
            float b[8] = {bf0.x, bf0.y, bf0.z, bf0.w, bf1.x, bf1.y, bf1.z, bf1.w};
#pragma unroll
            for (int i = 0; i < 8; i++)
#pragma unroll
                for (int j = 0; j < 8; j++)
                    acc[i][j] = fmaf(a[i], b[j], acc[i][j]);
        }
        __syncthreads();
    }

#pragma unroll
    for (int i = 0; i < 8; i++) {
        const int m = m0 + ty * 8 + i;
        const int t = m / BSZ;
        const int b = m % BSZ;
#pragma unroll
        for (int j = 0; j < 8; j++) {
            const int n = n0 + tx * 8 + j;
            float v = (acc[i][j] + bias[n]) * scale;
            if (mode == 0) {
                const int h = n >> 6, d = n & 63;
                C[(((size_t)b * NH + h) * T_LEN + t) * HDIM + d] = v;
            } else {
                C[(size_t)m * EMB + n] = v;
            }
        }
    }
}

// ---------------------------------------------------------------------------
// Batched scores GEMM: S[z,q,k] = qh[z,q,:] . kh[z,k,:]   (z = b*NH + h, K=64)
// ---------------------------------------------------------------------------
__global__ __launch_bounds__(256) void sgemm_scores()
{
    const int z = blockIdx.z;
    const float* A = g_q + (size_t)z * T_LEN * HDIM;
    const float* B = g_k + (size_t)z * T_LEN * HDIM;
    float*       C = g_S + (size_t)z * T_LEN * T_LEN;

    __shared__ float As[8][132];
    __shared__ float Bs[8][132];

    const int tid = threadIdx.x;
    const int m0  = blockIdx.y * 128;
    const int n0  = blockIdx.x * 128;
    const int lr  = tid >> 1;
    const int lc  = (tid & 1) * 4;
    const int ty  = tid >> 4;
    const int tx  = tid & 15;

    const float* Aptr = A + (size_t)(m0 + lr) * HDIM + lc;
    const float* Bptr = B + (size_t)(n0 + lr) * HDIM + lc;

    float acc[8][8];
#pragma unroll
    for (int i = 0; i < 8; i++)
#pragma unroll
        for (int j = 0; j < 8; j++) acc[i][j] = 0.0f;

    for (int k0 = 0; k0 < HDIM; k0 += 8) {
        float4 a4 = *(const float4*)(Aptr + k0);
        float4 b4 = *(const float4*)(Bptr + k0);
        As[lc + 0][lr] = a4.x; As[lc + 1][lr] = a4.y;
        As[lc + 2][lr] = a4.z; As[lc + 3][lr] = a4.w;
        Bs[lc + 0][lr] = b4.x; Bs[lc + 1][lr] = b4.y;
        Bs[lc + 2][lr] = b4.z; Bs[lc + 3][lr] = b4.w;
        __syncthreads();
#pragma unroll
        for (int kk = 0; kk < 8; kk++) {
            float4 af0 = *(const float4*)&As[kk][ty * 8];
            float4 af1 = *(const float4*)&As[kk][ty * 8 + 4];
            float4 bf0 = *(const float4*)&Bs[kk][tx * 8];
            float4 bf1 = *(const float4*)&Bs[kk][tx * 8 + 4];
            float a[8] = {af0.x, af0.y, af0.z, af0.w, af1.x, af1.y, af1.z, af1.w};
            float b[8] = {bf0.x, bf0.y, bf0.z, bf0.w, bf1.x, bf1.y, bf1.z, bf1.w};
#pragma unroll
            for (int i = 0; i < 8; i++)
#pragma unroll
                for (int j = 0; j < 8; j++)
                    acc[i][j] = fmaf(a[i], b[j], acc[i][j]);
        }
        __syncthreads();
    }

#pragma unroll
    for (int i = 0; i < 8; i++) {
        const size_t q = m0 + ty * 8 + i;
#pragma unroll
        for (int j = 0; j < 8; j++)
            C[q * T_LEN + n0 + tx * 8 + j] = acc[i][j];
    }
}

// ---------------------------------------------------------------------------
// Fused softmax (per head row, in-place on g_S) + average over heads.
// One CTA per (b,q). 16 warps = 16 heads. smem holds all 16 prob rows.
// ---------------------------------------------------------------------------
__global__ __launch_bounds__(512) void softmax_avg(float* __restrict__ avg_out)
{
    extern __shared__ float buf[];   // [NH][T_LEN]
    const int bq   = blockIdx.x;
    const int b    = bq / T_LEN;
    const int q    = bq % T_LEN;
    const int w    = threadIdx.x >> 5;   // head
    const int lane = threadIdx.x & 31;

    float* mybuf = buf + (size_t)w * T_LEN;
    float* row   = g_S + (((size_t)b * NH + w) * T_LEN + q) * T_LEN;

    float vals[64];
    float mx = -1e30f;
#pragma unroll
    for (int j = 0; j < 64; j++) {
        float v = row[j * 32 + lane];
        vals[j] = v;
        mx = fmaxf(mx, v);
    }
#pragma unroll
    for (int o = 16; o > 0; o >>= 1)
        mx = fmaxf(mx, __shfl_xor_sync(0xffffffffu, mx, o));

    float s = 0.0f;
#pragma unroll
    for (int j = 0; j < 64; j++) {
        float e = __expf(vals[j] - mx);
        vals[j] = e;
        s += e;
    }
#pragma unroll
    for (int o = 16; o > 0; o >>= 1)
        s += __shfl_xor_sync(0xffffffffu, s, o);
    const float inv = 1.0f / s;

#pragma unroll
    for (int j = 0; j < 64; j++) {
        float p = vals[j] * inv;
        mybuf[j * 32 + lane] = p;
        row[j * 32 + lane]   = p;
    }
    __syncthreads();

    // average over heads -> avg_out[b][q][k]
    for (int idx = threadIdx.x; idx < T_LEN; idx += 512) {
        float a = 0.0f;
#pragma unroll
        for (int hh = 0; hh < NH; hh++)
            a += buf[(size_t)hh * T_LEN + idx];
        avg_out[((size_t)b * T_LEN + q) * T_LEN + idx] = a * (1.0f / NH);
    }
}

// ---------------------------------------------------------------------------
// Batched NN GEMM: ctx[z,q,d] = sum_k S[z,q,k] * v[z,k,d]   (N=64)
// BM=128, BN=64, BK=16, 256 threads, 8x4 microtile. Output -> [T,B,E].
// ---------------------------------------------------------------------------
__global__ __launch_bounds__(256) void sgemm_ctx()
{
    const int z = blockIdx.y;
    const int b = z / NH, h = z % NH;
    const float* A = g_S + (size_t)z * T_LEN * T_LEN;
    const float* V = g_v + (size_t)z * T_LEN * HDIM;

    __shared__ float As[16][132];
    __shared__ float Vs[16][64];

    const int tid = threadIdx.x;
    const int m0  = blockIdx.x * 128;
    const int ty  = tid >> 4;
    const int tx  = tid & 15;

    float acc[8][4];
#pragma unroll
    for (int i = 0; i < 8; i++)
#pragma unroll
        for (int j = 0; j < 4; j++) acc[i][j] = 0.0f;

    for (int k0 = 0; k0 < T_LEN; k0 += 16) {
#pragma unroll
        for (int i = 0; i < 2; i++) {
            const int f = tid + i * 256;
            const int r = f >> 2;
            const int c = (f & 3) * 4;
            float4 a4 = *(const float4*)(A + (size_t)(m0 + r) * T_LEN + k0 + c);
            As[c + 0][r] = a4.x; As[c + 1][r] = a4.y;
            As[c + 2][r] = a4.z; As[c + 3][r] = a4.w;
        }
        {
            const int r = tid >> 4;        // k within tile
            const int c = (tid & 15) * 4;  // d
            float4 v4 = *(const float4*)(V + (size_t)(k0 + r) * HDIM + c);
            *(float4*)&Vs[r][c] = v4;
        }
        __syncthreads();
#pragma unroll
        for (int kk = 0; kk < 16; kk++) {
            float4 af0 = *(const float4*)&As[kk][ty * 8];
            float4 af1 = *(const float4*)&As[kk][ty * 8 + 4];
            float4 bf  = *(const float4*)&Vs[kk][tx * 4];
            float a[8] = {af0.x, af0.y, af0.z, af0.w, af1.x, af1.y, af1.z, af1.w};
            float bb[4] = {bf.x, bf.y, bf.z, bf.w};
#pragma unroll
            for (int i = 0; i < 8; i++)
#pragma unroll
                for (int j = 0; j < 4; j++)
                    acc[i][j] = fmaf(a[i], bb[j], acc[i][j]);
        }
        __syncthreads();
    }

#pragma unroll
    for (int i = 0; i < 8; i++) {
        const int qrow = m0 + ty * 8 + i;
#pragma unroll
        for (int j = 0; j < 4; j++) {
            const int d = tx * 4 + j;
            g_ctx[((size_t)qrow * BSZ + b) * EMB + h * HDIM + d] = acc[i][j];
        }
    }
}

// ---------------------------------------------------------------------------
// Launch
// ---------------------------------------------------------------------------
extern "C" void kernel_launch(void* const* d_in, const int* in_sizes, int n_in,
                              void* d_out, int out_size)
{
    const float* X  = (const float*)d_in[0];
    const float* wq = (const float*)d_in[1];
    const float* bq = (const float*)d_in[2];
    const float* wk = (const float*)d_in[3];
    const float* bk = (const float*)d_in[4];
    const float* wv = (const float*)d_in[5];
    const float* bv = (const float*)d_in[6];
    const float* wo = (const float*)d_in[7];
    const float* bo = (const float*)d_in[8];

    float* out = (float*)d_out;                              // [T,B,E]
    float* avg = out + (size_t)T_LEN * BSZ * EMB;            // [B,Tq,Tk]

    float *qp, *kp, *vp, *ctxp;
    cudaGetSymbolAddress((void**)&qp,   g_q);
    cudaGetSymbolAddress((void**)&kp,   g_k);
    cudaGetSymbolAddress((void**)&vp,   g_v);
    cudaGetSymbolAddress((void**)&ctxp, g_ctx);

    cudaFuncSetAttribute(softmax_avg,
                         cudaFuncAttributeMaxDynamicSharedMemorySize,
                         NH * T_LEN * (int)sizeof(float));

    const float scaling = 0.125f;   // HD^-0.5

    dim3 gProj(EMB / 128, MROWS / 128);       // (8, 64)
    sgemm_nt<<<gProj, 256>>>(X, wq, bq, qp, scaling, 0);
    sgemm_nt<<<gProj, 256>>>(X, wk, bk, kp, 1.0f,    0);
    sgemm_nt<<<gProj, 256>>>(X, wv, bv, vp, 1.0f,    0);

    dim3 gScores(T_LEN / 128, T_LEN / 128, BH);   // (16,16,64)
    sgemm_scores<<<gScores, 256>>>();

    softmax_avg<<<BSZ * T_LEN, 512, NH * T_LEN * (int)sizeof(float)>>>(avg);

    dim3 gCtx(T_LEN / 128, BH);                   // (16,64)
    sgemm_ctx<<<gCtx, 256>>>();

    sgemm_nt<<<gProj, 256>>>(ctxp, wo, bo, out, 1.0f, 1);
}

// round 2
// speedup vs baseline: 2.3235x; 2.3235x over previous
#include <cuda_runtime.h>
#include <cstdint>
#include <cstddef>

#define T_LEN 2048
#define BSZ   4
#define EMB   1024
#define NH    16
#define HDIM  64
#define MROWS (T_LEN * BSZ)   // 8192
#define BH    (BSZ * NH)      // 64

// ---------------------------------------------------------------------------
// Scratch (device globals)
// ---------------------------------------------------------------------------
__device__ float g_q  [(size_t)BH * T_LEN * HDIM];   // [z][t][d]
__device__ float g_k  [(size_t)BH * T_LEN * HDIM];   // [z][t][d]
__device__ float g_vt [(size_t)BH * HDIM * T_LEN];   // [z][d][t]  (transposed V)
__device__ float g_ctx[(size_t)MROWS * EMB];         // [t*B+b][e]
__device__ float g_S  [(size_t)BH * T_LEN * T_LEN];  // raw scores, 1 GiB
__device__ float g_rm [(size_t)BH * T_LEN];          // row max
__device__ float g_rz [(size_t)BH * T_LEN];          // row 1/sum

// ---------------------------------------------------------------------------
// tf32 helpers
// ---------------------------------------------------------------------------
__device__ __forceinline__ uint32_t f2tf(float x) {
    uint32_t r; asm("cvt.rna.tf32.f32 %0, %1;" : "=r"(r) : "f"(x)); return r;
}
__device__ __forceinline__ void mma8(float* d, const uint32_t* a, const uint32_t* b) {
    asm volatile(
        "mma.sync.aligned.m16n8k8.row.col.f32.tf32.tf32.f32 "
        "{%0,%1,%2,%3}, {%4,%5,%6,%7}, {%8,%9}, {%0,%1,%2,%3};"
        : "+f"(d[0]), "+f"(d[1]), "+f"(d[2]), "+f"(d[3])
        : "r"(a[0]), "r"(a[1]), "r"(a[2]), "r"(a[3]), "r"(b[0]), "r"(b[1]));
}

// ---------------------------------------------------------------------------
// Projection GEMM (tf32): C = (A[M,K] @ W[N,K]^T + bias) * scale
// K = 1024. BM=BN=128, BK=32, 256 threads, warp grid 2(m) x 4(n), warp 64x32.
// mode 0: [z][t][d] layout (q/k), mode 2: transposed V [z][d][t], mode 3: plain
// ---------------------------------------------------------------------------
__global__ __launch_bounds__(256) void gemm_proj(
    const float* __restrict__ A, const float* __restrict__ W,
    const float* __restrict__ bias, float* __restrict__ C,
    float scale, int mode)
{
    __shared__ uint32_t As[128 * 36];
    __shared__ uint32_t Ws[128 * 36];

    const int tid  = threadIdx.x;
    const int warp = tid >> 5, lane = tid & 31;
    const int g    = lane >> 2, tg = lane & 3;
    const int wm   = warp >> 2, wn = warp & 3;     // 2 x 4
    const int m0   = blockIdx.y * 128;
    const int n0   = blockIdx.x * 128;
    const int lr   = tid >> 1;
    const int lc   = (tid & 1) * 16;

    float acc[4][4][4];
#pragma unroll
    for (int i = 0; i < 4; i++)
#pragma unroll
        for (int j = 0; j < 4; j++)
#pragma unroll
            for (int c = 0; c < 4; c++) acc[i][j][c] = 0.0f;

    const float* Ap = A + (size_t)(m0 + lr) * EMB + lc;
    const float* Wp = W + (size_t)(n0 + lr) * EMB + lc;

    for (int k0 = 0; k0 < EMB; k0 += 32) {
#pragma unroll
        for (int v = 0; v < 4; v++) {
            float4 a4 = *(const float4*)(Ap + k0 + v * 4);
            As[lr * 36 + lc + v * 4 + 0] = f2tf(a4.x);
            As[lr * 36 + lc + v * 4 + 1] = f2tf(a4.y);
            As[lr * 36 + lc + v * 4 + 2] = f2tf(a4.z);
            As[lr * 36 + lc + v * 4 + 3] = f2tf(a4.w);
            float4 w4 = *(const float4*)(Wp + k0 + v * 4);
            Ws[lr * 36 + lc + v * 4 + 0] = f2tf(w4.x);
            Ws[lr * 36 + lc + v * 4 + 1] = f2tf(w4.y);
            Ws[lr * 36 + lc + v * 4 + 2] = f2tf(w4.z);
            Ws[lr * 36 + lc + v * 4 + 3] = f2tf(w4.w);
        }
        __syncthreads();
#pragma unroll
        for (int kk = 0; kk < 32; kk += 8) {
            uint32_t af[4][4], bf[4][2];
#pragma unroll
            for (int mb = 0; mb < 4; mb++) {
                const int r = wm * 64 + mb * 16;
                af[mb][0] = As[(r + g    ) * 36 + kk + tg    ];
                af[mb][1] = As[(r + g + 8) * 36 + kk + tg    ];
                af[mb][2] = As[(r + g    ) * 36 + kk + tg + 4];
                af[mb][3] = As[(r + g + 8) * 36 + kk + tg + 4];
            }
#pragma unroll
            for (int nb = 0; nb < 4; nb++) {
                const int r = wn * 32 + nb * 8 + g;
                bf[nb][0] = Ws[r * 36 + kk + tg    ];
                bf[nb][1] = Ws[r * 36 + kk + tg + 4];
            }
#pragma unroll
            for (int mb = 0; mb < 4; mb++)
#pragma unroll
                for (int nb = 0; nb < 4; nb++)
                    mma8(acc[mb][nb], af[mb], bf[nb]);
        }
        __syncthreads();
    }

    // epilogue
#pragma unroll
    for (int mb = 0; mb < 4; mb++) {
#pragma unroll
        for (int nb = 0; nb < 4; nb++) {
            const int n = n0 + wn * 32 + nb * 8 + tg * 2;
            const float b0 = bias[n], b1 = bias[n + 1];
#pragma unroll
            for (int half = 0; half < 2; half++) {
                const int m = m0 + wm * 64 + mb * 16 + g + half * 8;
                const float v0 = (acc[mb][nb][half * 2 + 0] + b0) * scale;
                const float v1 = (acc[mb][nb][half * 2 + 1] + b1) * scale;
                const int t = m >> 2;       // m / BSZ
                const int b = m & 3;        // m % BSZ
                if (mode == 0) {
                    const int h = n >> 6, d = n & 63;
                    float* dst = C + (((size_t)b * NH + h) * T_LEN + t) * HDIM + d;
                    dst[0] = v0; dst[1] = v1;
                } else if (mode == 2) {
                    const int h = n >> 6, d = n & 63;
                    float* dst = C + (((size_t)b * NH + h) * HDIM + d) * T_LEN + t;
                    dst[0] = v0; dst[T_LEN] = v1;
                } else {
                    float* dst = C + (size_t)m * EMB + n;
                    dst[0] = v0; dst[1] = v1;
                }
            }
        }
    }
}

// ---------------------------------------------------------------------------
// Scores GEMM (tf32): S[z,q,k] = q[z,q,:] . k[z,k,:],  K = 64
// BM=BN=128, BK=32 (2 iters), same warp layout as gemm_proj.
// ---------------------------------------------------------------------------
__global__ __launch_bounds__(256) void gemm_scores()
{
    __shared__ uint32_t As[128 * 36];
    __shared__ uint32_t Bs[128 * 36];

    const int z    = blockIdx.z;
    const float* A = g_q + (size_t)z * T_LEN * HDIM;
    const float* B = g_k + (size_t)z * T_LEN * HDIM;
    float*       Co = g_S + (size_t)z * T_LEN * T_LEN;

    const int tid  = threadIdx.x;
    const int warp = tid >> 5, lane = tid & 31;
    const int g    = lane >> 2, tg = lane & 3;
    const int wm   = warp >> 2, wn = warp & 3;
    const int m0   = blockIdx.y * 128;
    const int n0   = blockIdx.x * 128;
    const int lr   = tid >> 1;
    const int lc   = (tid & 1) * 16;

    float acc[4][4][4];
#pragma unroll
    for (int i = 0; i < 4; i++)
#pragma unroll
        for (int j = 0; j < 4; j++)
#pragma unroll
            for (int c = 0; c < 4; c++) acc[i][j][c] = 0.0f;

    const float* Ap = A + (size_t)(m0 + lr) * HDIM + lc;
    const float* Bp = B + (size_t)(n0 + lr) * HDIM + lc;

    for (int k0 = 0; k0 < HDIM; k0 += 32) {
#pragma unroll
        for (int v = 0; v < 4; v++) {
            float4 a4 = *(const float4*)(Ap + k0 + v * 4);
            As[lr * 36 + lc + v * 4 + 0] = f2tf(a4.x);
            As[lr * 36 + lc + v * 4 + 1] = f2tf(a4.y);
            As[lr * 36 + lc + v * 4 + 2] = f2tf(a4.z);
            As[lr * 36 + lc + v * 4 + 3] = f2tf(a4.w);
            float4 b4 = *(const float4*)(Bp + k0 + v * 4);
            Bs[lr * 36 + lc + v * 4 + 0] = f2tf(b4.x);
            Bs[lr * 36 + lc + v * 4 + 1] = f2tf(b4.y);
            Bs[lr * 36 + lc + v * 4 + 2] = f2tf(b4.z);
            Bs[lr * 36 + lc + v * 4 + 3] = f2tf(b4.w);
        }
        __syncthreads();
#pragma unroll
        for (int kk = 0; kk < 32; kk += 8) {
            uint32_t af[4][4], bf[4][2];
#pragma unroll
            for (int mb = 0; mb < 4; mb++) {
                const int r = wm * 64 + mb * 16;
                af[mb][0] = As[(r + g    ) * 36 + kk + tg    ];
                af[mb][1] = As[(r + g + 8) * 36 + kk + tg    ];
                af[mb][2] = As[(r + g    ) * 36 + kk + tg + 4];
                af[mb][3] = As[(r + g + 8) * 36 + kk + tg + 4];
            }
#pragma unroll
            for (int nb = 0; nb < 4; nb++) {
                const int r = wn * 32 + nb * 8 + g;
                bf[nb][0] = Bs[r * 36 + kk + tg    ];
                bf[nb][1] = Bs[r * 36 + kk + tg + 4];
            }
#pragma unroll
            for (int mb = 0; mb < 4; mb++)
#pragma unroll
                for (int nb = 0; nb < 4; nb++)
                    mma8(acc[mb][nb], af[mb], bf[nb]);
        }
        __syncthreads();
    }

#pragma unroll
    for (int mb = 0; mb < 4; mb++)
#pragma unroll
        for (int nb = 0; nb < 4; nb++) {
            const int n = n0 + wn * 32 + nb * 8 + tg * 2;
#pragma unroll
            for (int half = 0; half < 2; half++) {
                const size_t m = m0 + wm * 64 + mb * 16 + g + half * 8;
                float* dst = Co + m * T_LEN + n;
                dst[0] = acc[mb][nb][half * 2 + 0];
                dst[1] = acc[mb][nb][half * 2 + 1];
            }
        }
}

// ---------------------------------------------------------------------------
// Softmax stats + head-average. One CTA per (b,q), 16 warps = 16 heads.
// Writes (rowmax, 1/rowsum) stats + avg_attn; does NOT write probs.
// ---------------------------------------------------------------------------
__global__ __launch_bounds__(512) void softmax_stats_avg(float* __restrict__ avg_out)
{
    extern __shared__ float buf[];   // [NH][T_LEN]
    const int bq   = blockIdx.x;
    const int b    = bq / T_LEN;
    const int q    = bq % T_LEN;
    const int w    = threadIdx.x >> 5;   // head
    const int lane = threadIdx.x & 31;

    float* mybuf = buf + (size_t)w * T_LEN;
    const float* row = g_S + (((size_t)b * NH + w) * T_LEN + q) * T_LEN;

    float vals[64];
    float mx = -1e30f;
#pragma unroll
    for (int j = 0; j < 64; j++) {
        float v = row[j * 32 + lane];
        vals[j] = v;
        mx = fmaxf(mx, v);
    }
#pragma unroll
    for (int o = 16; o > 0; o >>= 1)
        mx = fmaxf(mx, __shfl_xor_sync(0xffffffffu, mx, o));

    float s = 0.0f;
#pragma unroll
    for (int j = 0; j < 64; j++) {
        float e = __expf(vals[j] - mx);
        vals[j] = e;
        s += e;
    }
#pragma unroll
    for (int o = 16; o > 0; o >>= 1)
        s += __shfl_xor_sync(0xffffffffu, s, o);
    const float inv = 1.0f / s;

    if (lane == 0) {
        g_rm[((size_t)b * NH + w) * T_LEN + q] = mx;
        g_rz[((size_t)b * NH + w) * T_LEN + q] = inv;
    }

#pragma unroll
    for (int j = 0; j < 64; j++)
        mybuf[j * 32 + lane] = vals[j] * inv;
    __syncthreads();

    for (int idx = threadIdx.x; idx < T_LEN; idx += 512) {
        float a = 0.0f;
#pragma unroll
        for (int hh = 0; hh < NH; hh++)
            a += buf[(size_t)hh * T_LEN + idx];
        avg_out[((size_t)b * T_LEN + q) * T_LEN + idx] = a * (1.0f / NH);
    }
}

// ---------------------------------------------------------------------------
// Context GEMM (tf32): ctx[z,q,d] = sum_k exp(S[z,q,k]-m)*invZ * V[z,k,d]
// A = softmaxed-S (computed inline), B = Vt[z][d][t] (NT form).
// BM=128, BN=64, BK=32, warps 4(m) x 2(n), warp tile 32x32.
// ---------------------------------------------------------------------------
__global__ __launch_bounds__(256) void gemm_ctx()
{
    __shared__ uint32_t As[128 * 36];
    __shared__ uint32_t Vs[64 * 36];

    const int z = blockIdx.y;
    const int b = z >> 4, h = z & 15;
    const float* Sp = g_S  + (size_t)z * T_LEN * T_LEN;
    const float* Vp = g_vt + (size_t)z * HDIM * T_LEN;

    const int tid  = threadIdx.x;
    const int warp = tid >> 5, lane = tid & 31;
    const int g    = lane >> 2, tg = lane & 3;
    const int wm   = warp >> 1, wn = warp & 1;   // 4 x 2
    const int m0   = blockIdx.x * 128;
    const int lr   = tid >> 1;
    const int lc   = (tid & 1) * 16;
    const int vr   = tid >> 2;           // 0..63
    const int vc   = (tid & 3) * 8;      // 0..24

    const float rm = g_rm[(size_t)z * T_LEN + m0 + lr];
    const float rz = g_rz[(size_t)z * T_LEN + m0 + lr];

    float acc[2][4][4];
#pragma unroll
    for (int i = 0; i < 2; i++)
#pragma unroll
        for (int j = 0; j < 4; j++)
#pragma unroll
            for (int c = 0; c < 4; c++) acc[i][j][c] = 0.0f;

    const float* Ap = Sp + (size_t)(m0 + lr) * T_LEN + lc;
    const float* Bp = Vp + (size_t)vr * T_LEN + vc;

    for (int k0 = 0; k0 < T_LEN; k0 += 32) {
#pragma unroll
        for (int v = 0; v < 4; v++) {
            float4 a4 = *(const float4*)(Ap + k0 + v * 4);
            As[lr * 36 + lc + v * 4 + 0] = f2tf(__expf(a4.x - rm) * rz);
            As[lr * 36 + lc + v * 4 + 1] = f2tf(__expf(a4.y - rm) * rz);
            As[lr * 36 + lc + v * 4 + 2] = f2tf(__expf(a4.z - rm) * rz);
            As[lr * 36 + lc + v * 4 + 3] = f2tf(__expf(a4.w - rm) * rz);
        }
#pragma unroll
        for (int v = 0; v < 2; v++) {
            float4 b4 = *(const float4*)(Bp + k0 + v * 4);
            Vs[vr * 36 + vc + v * 4 + 0] = f2tf(b4.x);
            Vs[vr * 36 + vc + v * 4 + 1] = f2tf(b4.y);
            Vs[vr * 36 + vc + v * 4 + 2] = f2tf(b4.z);
            Vs[vr * 36 + vc + v * 4 + 3] = f2tf(b4.w);
        }
        __syncthreads();
#pragma unroll
        for (int kk = 0; kk < 32; kk += 8) {
            uint32_t af[2][4], bf[4][2];
#pragma unroll
            for (int mb = 0; mb < 2; mb++) {
                const int r = wm * 32 + mb * 16;
                af[mb][0] = As[(r + g    ) * 36 + kk + tg    ];
                af[mb][1] = As[(r + g + 8) * 36 + kk + tg    ];
                af[mb][2] = As[(r + g    ) * 36 + kk + tg + 4];
                af[mb][3] = As[(r + g + 8) * 36 + kk + tg + 4];
            }
#pragma unroll
            for (int nb = 0; nb < 4; nb++) {
                const int r = wn * 32 + nb * 8 + g;
                bf[nb][0] = Vs[r * 36 + kk + tg    ];
                bf[nb][1] = Vs[r * 36 + kk + tg + 4];
            }
#pragma unroll
            for (int mb = 0; mb < 2; mb++)
#pragma unroll
                for (int nb = 0; nb < 4; nb++)
                    mma8(acc[mb][nb], af[mb], bf[nb]);
        }
        __syncthreads();
    }

#pragma unroll
    for (int mb = 0; mb < 2; mb++)
#pragma unroll
        for (int nb = 0; nb < 4; nb++) {
            const int d = wn * 32 + nb * 8 + tg * 2;
#pragma unroll
            for (int half = 0; half < 2; half++) {
                const int q = m0 + wm * 32 + mb * 16 + g + half * 8;
                float* dst = g_ctx + ((size_t)q * BSZ + b) * EMB + h * HDIM + d;
                dst[0] = acc[mb][nb][half * 2 + 0];
                dst[1] = acc[mb][nb][half * 2 + 1];
            }
        }
}

// ---------------------------------------------------------------------------
// Launch
// ---------------------------------------------------------------------------
extern "C" void kernel_launch(void* const* d_in, const int* in_sizes, int n_in,
                              void* d_out, int out_size)
{
    const float* X  = (const float*)d_in[0];
    const float* wq = (const float*)d_in[1];
    const float* bq = (const float*)d_in[2];
    const float* wk = (const float*)d_in[3];
    const float* bk = (const float*)d_in[4];
    const float* wv = (const float*)d_in[5];
    const float* bv = (const float*)d_in[6];
    const float* wo = (const float*)d_in[7];
    const float* bo = (const float*)d_in[8];

    float* out = (float*)d_out;                    // [T,B,E]
    float* avg = out + (size_t)T_LEN * BSZ * EMB;  // [B,Tq,Tk]

    float *qp, *kp, *vtp, *ctxp;
    cudaGetSymbolAddress((void**)&qp,   g_q);
    cudaGetSymbolAddress((void**)&kp,   g_k);
    cudaGetSymbolAddress((void**)&vtp,  g_vt);
    cudaGetSymbolAddress((void**)&ctxp, g_ctx);

    cudaFuncSetAttribute(softmax_stats_avg,
                         cudaFuncAttributeMaxDynamicSharedMemorySize,
                         NH * T_LEN * (int)sizeof(float));

    const float scaling = 0.125f;   // HD^-0.5

    dim3 gProj(EMB / 128, MROWS / 128);            // (8, 64)
    gemm_proj<<<gProj, 256>>>(X, wq, bq, qp,  scaling, 0);
    gemm_proj<<<gProj, 256>>>(X, wk, bk, kp,  1.0f,    0);
    gemm_proj<<<gProj, 256>>>(X, wv, bv, vtp, 1.0f,    2);

    dim3 gScores(T_LEN / 128, T_LEN / 128, BH);    // (16,16,64)
    gemm_scores<<<gScores, 256>>>();

    softmax_stats_avg<<<BSZ * T_LEN, 512, NH * T_LEN * (int)sizeof(float)>>>(avg);

    dim3 gCtx(T_LEN / 128, BH);                    // (16,64)
    gemm_ctx<<<gCtx, 256>>>();

    gemm_proj<<<gProj, 256>>>(ctxp, wo, bo, out, 1.0f, 3);
}

// round 3
// speedup vs baseline: 2.4014x; 1.0335x over previous
#include <cuda_runtime.h>
#include <cstdint>
#include <cstddef>

#define T_LEN 2048
#define BSZ   4
#define EMB   1024
#define NH    16
#define HDIM  64
#define MROWS (T_LEN * BSZ)   // 8192
#define BH    (BSZ * NH)      // 64

// ---------------------------------------------------------------------------
// Scratch (device globals)
// ---------------------------------------------------------------------------
__device__ float g_q  [(size_t)BH * T_LEN * HDIM];   // [z][t][d]
__device__ float g_k  [(size_t)BH * T_LEN * HDIM];   // [z][t][d]
__device__ float g_vt [(size_t)BH * HDIM * T_LEN];   // [z][d][t]
__device__ float g_ctx[(size_t)MROWS * EMB];         // [t*B+b][e]
__device__ float g_S  [(size_t)BH * T_LEN * T_LEN];  // raw scores, 1 GiB
__device__ float g_rm [(size_t)BH * T_LEN];          // row max
__device__ float g_rz [(size_t)BH * T_LEN];          // row 1/sum

// ---------------------------------------------------------------------------
// helpers
// ---------------------------------------------------------------------------
__device__ __forceinline__ uint32_t f2tf(float x) {
    uint32_t r; asm("cvt.rna.tf32.f32 %0, %1;" : "=r"(r) : "f"(x)); return r;
}
__device__ __forceinline__ void mma8(float* d, const uint32_t* a, const uint32_t* b) {
    asm volatile(
        "mma.sync.aligned.m16n8k8.row.col.f32.tf32.tf32.f32 "
        "{%0,%1,%2,%3}, {%4,%5,%6,%7}, {%8,%9}, {%0,%1,%2,%3};"
        : "+f"(d[0]), "+f"(d[1]), "+f"(d[2]), "+f"(d[3])
        : "r"(a[0]), "r"(a[1]), "r"(a[2]), "r"(a[3]), "r"(b[0]), "r"(b[1]));
}
__device__ __forceinline__ uint32_t sptr(const void* p) {
    return (uint32_t)__cvta_generic_to_shared(p);
}
// ldmatrix.x4 of b16 8x8 tiles == four 8x4 tf32 tiles (one 32b word per thread)
__device__ __forceinline__ void ldsm4(uint32_t* r, uint32_t addr) {
    asm volatile("ldmatrix.sync.aligned.m8n8.x4.shared.b16 {%0,%1,%2,%3}, [%4];"
                 : "=r"(r[0]), "=r"(r[1]), "=r"(r[2]), "=r"(r[3]) : "r"(addr));
}

#define LDA 36   // row stride (u32) for 32-wide k tiles (+4 pad)

// ---------------------------------------------------------------------------
// Projection GEMM (tf32): C = (A[M,K] @ W[N,K]^T + bias) * scale, K=1024
// BM=BN=128, BK=32, 256 thr, warps 2(m) x 4(n), warp tile 64x32.
// mode 0: q/k -> [z][t][d]; mode 2: V -> [z][d][t]; mode 3: plain [M,E]
// qkv=1: blockIdx.z selects (wq,bq)/(wk,bk)/(wv,bv) with per-z mode/scale.
// ---------------------------------------------------------------------------
__global__ __launch_bounds__(256, 2) void gemm_proj(
    const float* __restrict__ A,
    const float* __restrict__ W0, const float* __restrict__ b0_,
    const float* __restrict__ W1, const float* __restrict__ b1_,
    const float* __restrict__ W2, const float* __restrict__ b2_,
    float* __restrict__ C0, float* __restrict__ C1, float* __restrict__ C2,
    int qkv)
{
    __shared__ __align__(16) uint32_t As[128 * LDA];
    __shared__ __align__(16) uint32_t Ws[128 * LDA];

    const float* W; const float* bias; float* C; float scale; int mode;
    if (qkv) {
        if (blockIdx.z == 0)      { W = W0; bias = b0_; C = C0; scale = 0.125f; mode = 0; }
        else if (blockIdx.z == 1) { W = W1; bias = b1_; C = C1; scale = 1.0f;   mode = 0; }
        else                      { W = W2; bias = b2_; C = C2; scale = 1.0f;   mode = 2; }
    } else { W = W0; bias = b0_; C = C0; scale = 1.0f; mode = 3; }

    const int tid  = threadIdx.x;
    const int warp = tid >> 5, lane = tid & 31;
    const int g    = lane >> 2, tg = lane & 3;
    const int wm   = warp >> 2, wn = warp & 3;     // 2 x 4
    const int m0   = blockIdx.y * 128;
    const int n0   = blockIdx.x * 128;
    const int lr   = tid >> 1;
    const int lc   = (tid & 1) * 16;

    // ldmatrix lane-address components
    const int a_row = wm * 64 + (lane & 15);
    const int a_col = (lane >> 4) * 4;
    const int b_row = wn * 32 + ((lane >> 4) * 8) + (lane & 7);
    const int b_col = ((lane >> 3) & 1) * 4;
    const uint32_t sA = sptr(As), sW = sptr(Ws);

    float acc[4][4][4];
#pragma unroll
    for (int i = 0; i < 4; i++)
#pragma unroll
        for (int j = 0; j < 4; j++)
#pragma unroll
            for (int c = 0; c < 4; c++) acc[i][j][c] = 0.0f;

    const float* Ap = A + (size_t)(m0 + lr) * EMB + lc;
    const float* Wp = W + (size_t)(n0 + lr) * EMB + lc;

    for (int k0 = 0; k0 < EMB; k0 += 32) {
#pragma unroll
        for (int v = 0; v < 4; v++) {
            float4 a4 = *(const float4*)(Ap + k0 + v * 4);
            uint4 at = make_uint4(f2tf(a4.x), f2tf(a4.y), f2tf(a4.z), f2tf(a4.w));
            *(uint4*)&As[lr * LDA + lc + v * 4] = at;
            float4 w4 = *(const float4*)(Wp + k0 + v * 4);
            uint4 wt = make_uint4(f2tf(w4.x), f2tf(w4.y), f2tf(w4.z), f2tf(w4.w));
            *(uint4*)&Ws[lr * LDA + lc + v * 4] = wt;
        }
        __syncthreads();
#pragma unroll
        for (int kk = 0; kk < 32; kk += 8) {
            uint32_t af[4][4], bf[4][2];
#pragma unroll
            for (int mb = 0; mb < 4; mb++)
                ldsm4(af[mb], sA + (((a_row + mb * 16) * LDA) + kk + a_col) * 4u);
#pragma unroll
            for (int p = 0; p < 2; p++) {
                uint32_t t[4];
                ldsm4(t, sW + (((b_row + p * 16) * LDA) + kk + b_col) * 4u);
                bf[2 * p][0] = t[0]; bf[2 * p][1] = t[1];
                bf[2 * p + 1][0] = t[2]; bf[2 * p + 1][1] = t[3];
            }
#pragma unroll
            for (int mb = 0; mb < 4; mb++)
#pragma unroll
                for (int nb = 0; nb < 4; nb++)
                    mma8(acc[mb][nb], af[mb], bf[nb]);
        }
        __syncthreads();
    }

#pragma unroll
    for (int mb = 0; mb < 4; mb++) {
#pragma unroll
        for (int nb = 0; nb < 4; nb++) {
            const int n = n0 + wn * 32 + nb * 8 + tg * 2;
            const float bb0 = bias[n], bb1 = bias[n + 1];
#pragma unroll
            for (int half = 0; half < 2; half++) {
                const int m = m0 + wm * 64 + mb * 16 + g + half * 8;
                const float v0 = (acc[mb][nb][half * 2 + 0] + bb0) * scale;
                const float v1 = (acc[mb][nb][half * 2 + 1] + bb1) * scale;
                const int t = m >> 2;       // m / BSZ
                const int b = m & 3;        // m % BSZ
                if (mode == 0) {
                    const int h = n >> 6, d = n & 63;
                    float* dst = C + (((size_t)b * NH + h) * T_LEN + t) * HDIM + d;
                    dst[0] = v0; dst[1] = v1;
                } else if (mode == 2) {
                    const int h = n >> 6, d = n & 63;
                    float* dst = C + (((size_t)b * NH + h) * HDIM + d) * T_LEN + t;
                    dst[0] = v0; dst[T_LEN] = v1;
                } else {
                    float* dst = C + (size_t)m * EMB + n;
                    dst[0] = v0; dst[1] = v1;
                }
            }
        }
    }
}

// ---------------------------------------------------------------------------
// Scores GEMM (tf32): S[z,q,k] = q[z,q,:] . k[z,k,:],  K = 64
// ---------------------------------------------------------------------------
__global__ __launch_bounds__(256, 2) void gemm_scores()
{
    __shared__ __align__(16) uint32_t As[128 * LDA];
    __shared__ __align__(16) uint32_t Bs[128 * LDA];

    const int z    = blockIdx.z;
    const float* A = g_q + (size_t)z * T_LEN * HDIM;
    const float* B = g_k + (size_t)z * T_LEN * HDIM;
    float*      Co = g_S + (size_t)z * T_LEN * T_LEN;

    const int tid  = threadIdx.x;
    const int warp = tid >> 5, lane = tid & 31;
    const int g    = lane >> 2, tg = lane & 3;
    const int wm   = warp >> 2, wn = warp & 3;
    const int m0   = blockIdx.y * 128;
    const int n0   = blockIdx.x * 128;
    const int lr   = tid >> 1;
    const int lc   = (tid & 1) * 16;

    const int a_row = wm * 64 + (lane & 15);
    const int a_col = (lane >> 4) * 4;
    const int b_row = wn * 32 + ((lane >> 4) * 8) + (lane & 7);
    const int b_col = ((lane >> 3) & 1) * 4;
    const uint32_t sA = sptr(As), sB = sptr(Bs);

    float acc[4][4][4];
#pragma unroll
    for (int i = 0; i < 4; i++)
#pragma unroll
        for (int j = 0; j < 4; j++)
#pragma unroll
            for (int c = 0; c < 4; c++) acc[i][j][c] = 0.0f;

    const float* Ap = A + (size_t)(m0 + lr) * HDIM + lc;
    const float* Bp = B + (size_t)(n0 + lr) * HDIM + lc;

    for (int k0 = 0; k0 < HDIM; k0 += 32) {
#pragma unroll
        for (int v = 0; v < 4; v++) {
            float4 a4 = *(const float4*)(Ap + k0 + v * 4);
            *(uint4*)&As[lr * LDA + lc + v * 4] =
                make_uint4(f2tf(a4.x), f2tf(a4.y), f2tf(a4.z), f2tf(a4.w));
            float4 b4 = *(const float4*)(Bp + k0 + v * 4);
            *(uint4*)&Bs[lr * LDA + lc + v * 4] =
                make_uint4(f2tf(b4.x), f2tf(b4.y), f2tf(b4.z), f2tf(b4.w));
        }
        __syncthreads();
#pragma unroll
        for (int kk = 0; kk < 32; kk += 8) {
            uint32_t af[4][4], bf[4][2];
#pragma unroll
            for (int mb = 0; mb < 4; mb++)
                ldsm4(af[mb], sA + (((a_row + mb * 16) * LDA) + kk + a_col) * 4u);
#pragma unroll
            for (int p = 0; p < 2; p++) {
                uint32_t t[4];
                ldsm4(t, sB + (((b_row + p * 16) * LDA) + kk + b_col) * 4u);
                bf[2 * p][0] = t[0]; bf[2 * p][1] = t[1];
                bf[2 * p + 1][0] = t[2]; bf[2 * p + 1][1] = t[3];
            }
#pragma unroll
            for (int mb = 0; mb < 4; mb++)
#pragma unroll
                for (int nb = 0; nb < 4; nb++)
                    mma8(acc[mb][nb], af[mb], bf[nb]);
        }
        __syncthreads();
    }

#pragma unroll
    for (int mb = 0; mb < 4; mb++)
#pragma unroll
        for (int nb = 0; nb < 4; nb++) {
            const int n = n0 + wn * 32 + nb * 8 + tg * 2;
#pragma unroll
            for (int half = 0; half < 2; half++) {
                const size_t m = m0 + wm * 64 + mb * 16 + g + half * 8;
                float* dst = Co + m * T_LEN + n;
                dst[0] = acc[mb][nb][half * 2 + 0];
                dst[1] = acc[mb][nb][half * 2 + 1];
            }
        }
}

// ---------------------------------------------------------------------------
// Softmax stats + head-average. One CTA per (b,q), 16 warps = 16 heads.
// ---------------------------------------------------------------------------
__global__ __launch_bounds__(512) void softmax_stats_avg(float* __restrict__ avg_out)
{
    extern __shared__ float buf[];   // [NH][T_LEN]
    const int bq   = blockIdx.x;
    const int b    = bq / T_LEN;
    const int q    = bq % T_LEN;
    const int w    = threadIdx.x >> 5;
    const int lane = threadIdx.x & 31;

    float* mybuf = buf + (size_t)w * T_LEN;
    const float* row = g_S + (((size_t)b * NH + w) * T_LEN + q) * T_LEN;

    float vals[64];
    float mx = -1e30f;
#pragma unroll
    for (int j = 0; j < 64; j++) {
        float v = row[j * 32 + lane];
        vals[j] = v;
        mx = fmaxf(mx, v);
    }
#pragma unroll
    for (int o = 16; o > 0; o >>= 1)
        mx = fmaxf(mx, __shfl_xor_sync(0xffffffffu, mx, o));

    float s = 0.0f;
#pragma unroll
    for (int j = 0; j < 64; j++) {
        float e = __expf(vals[j] - mx);
        vals[j] = e;
        s += e;
    }
#pragma unroll
    for (int o = 16; o > 0; o >>= 1)
        s += __shfl_xor_sync(0xffffffffu, s, o);
    const float inv = 1.0f / s;

    if (lane == 0) {
        g_rm[((size_t)b * NH + w) * T_LEN + q] = mx;
        g_rz[((size_t)b * NH + w) * T_LEN + q] = inv;
    }

#pragma unroll
    for (int j = 0; j < 64; j++)
        mybuf[j * 32 + lane] = vals[j] * inv;
    __syncthreads();

    for (int idx = threadIdx.x; idx < T_LEN; idx += 512) {
        float a = 0.0f;
#pragma unroll
        for (int hh = 0; hh < NH; hh++)
            a += buf[(size_t)hh * T_LEN + idx];
        avg_out[((size_t)b * T_LEN + q) * T_LEN + idx] = a * (1.0f / NH);
    }
}

// ---------------------------------------------------------------------------
// Context GEMM (tf32): ctx[z,q,d] = sum_k softmax(S)[q,k] * V[k,d]
// probs computed inline from raw S + (rm, rz). B = Vt[z][d][t].
// BM=128, BN=64, BK=32, warps 4(m) x 2(n), warp tile 32x32.
// ---------------------------------------------------------------------------
__global__ __launch_bounds__(256, 2) void gemm_ctx()
{
    __shared__ __align__(16) uint32_t As[128 * LDA];
    __shared__ __align__(16) uint32_t Vs[64 * LDA];

    const int z = blockIdx.y;
    const int b = z >> 4, h = z & 15;
    const float* Sp = g_S  + (size_t)z * T_LEN * T_LEN;
    const float* Vp = g_vt + (size_t)z * HDIM * T_LEN;

    const int tid  = threadIdx.x;
    const int warp = tid >> 5, lane = tid & 31;
    const int g    = lane >> 2, tg = lane & 3;
    const int wm   = warp >> 1, wn = warp & 1;   // 4 x 2
    const int m0   = blockIdx.x * 128;
    const int lr   = tid >> 1;
    const int lc   = (tid & 1) * 16;
    const int vr   = tid >> 2;           // 0..63
    const int vc   = (tid & 3) * 8;      // 0,8,16,24

    const int a_row = wm * 32 + (lane & 15);
    const int a_col = (lane >> 4) * 4;
    const int b_row = wn * 32 + ((lane >> 4) * 8) + (lane & 7);
    const int b_col = ((lane >> 3) & 1) * 4;
    const uint32_t sA = sptr(As), sV = sptr(Vs);

    const float rm = g_rm[(size_t)z * T_LEN + m0 + lr];
    const float rz = g_rz[(size_t)z * T_LEN + m0 + lr];

    float acc[2][4][4];
#pragma unroll
    for (int i = 0; i < 2; i++)
#pragma unroll
        for (int j = 0; j < 4; j++)
#pragma unroll
            for (int c = 0; c < 4; c++) acc[i][j][c] = 0.0f;

    const float* Ap = Sp + (size_t)(m0 + lr) * T_LEN + lc;
    const float* Bp = Vp + (size_t)vr * T_LEN + vc;

    for (int k0 = 0; k0 < T_LEN; k0 += 32) {
#pragma unroll
        for (int v = 0; v < 4; v++) {
            float4 a4 = *(const float4*)(Ap + k0 + v * 4);
            *(uint4*)&As[lr * LDA + lc + v * 4] = make_uint4(
                f2tf(__expf(a4.x - rm) * rz), f2tf(__expf(a4.y - rm) * rz),
                f2tf(__expf(a4.z - rm) * rz), f2tf(__expf(a4.w - rm) * rz));
        }
#pragma unroll
        for (int v = 0; v < 2; v++) {
            float4 b4 = *(const float4*)(Bp + k0 + v * 4);
            *(uint4*)&Vs[vr * LDA + vc + v * 4] =
                make_uint4(f2tf(b4.x), f2tf(b4.y), f2tf(b4.z), f2tf(b4.w));
        }
        __syncthreads();
#pragma unroll
        for (int kk = 0; kk < 32; kk += 8) {
            uint32_t af[2][4], bf[4][2];
#pragma unroll
            for (int mb = 0; mb < 2; mb++)
                ldsm4(af[mb], sA + (((a_row + mb * 16) * LDA) + kk + a_col) * 4u);
#pragma unroll
            for (int p = 0; p < 2; p++) {
                uint32_t t[4];
                ldsm4(t, sV + (((b_row + p * 16) * LDA) + kk + b_col) * 4u);
                bf[2 * p][0] = t[0]; bf[2 * p][1] = t[1];
                bf[2 * p + 1][0] = t[2]; bf[2 * p + 1][1] = t[3];
            }
#pragma unroll
            for (int mb = 0; mb < 2; mb++)
#pragma unroll
                for (int nb = 0; nb < 4; nb++)
                    mma8(acc[mb][nb], af[mb], bf[nb]);
        }
        __syncthreads();
    }

#pragma unroll
    for (int mb = 0; mb < 2; mb++)
#pragma unroll
        for (int nb = 0; nb < 4; nb++) {
            const int d = wn * 32 + nb * 8 + tg * 2;
#pragma unroll
            for (int half = 0; half < 2; half++) {
                const int q = m0 + wm * 32 + mb * 16 + g + half * 8;
                float* dst = g_ctx + ((size_t)q * BSZ + b) * EMB + h * HDIM + d;
                dst[0] = acc[mb][nb][half * 2 + 0];
                dst[1] = acc[mb][nb][half * 2 + 1];
            }
        }
}

// ---------------------------------------------------------------------------
// Launch
// ---------------------------------------------------------------------------
extern "C" void kernel_launch(void* const* d_in, const int* in_sizes, int n_in,
                              void* d_out, int out_size)
{
    const float* X  = (const float*)d_in[0];
    const float* wq = (const float*)d_in[1];
    const float* bq = (const float*)d_in[2];
    const float* wk = (const float*)d_in[3];
    const float* bk = (const float*)d_in[4];
    const float* wv = (const float*)d_in[5];
    const float* bv = (const float*)d_in[6];
    const float* wo = (const float*)d_in[7];
    const float* bo = (const float*)d_in[8];

    float* out = (float*)d_out;                    // [T,B,E]
    float* avg = out + (size_t)T_LEN * BSZ * EMB;  // [B,Tq,Tk]

    float *qp, *kp, *vtp, *ctxp;
    cudaGetSymbolAddress((void**)&qp,   g_q);
    cudaGetSymbolAddress((void**)&kp,   g_k);
    cudaGetSymbolAddress((void**)&vtp,  g_vt);
    cudaGetSymbolAddress((void**)&ctxp, g_ctx);

    cudaFuncSetAttribute(softmax_stats_avg,
                         cudaFuncAttributeMaxDynamicSharedMemorySize,
                         NH * T_LEN * (int)sizeof(float));

    // fused q,k,v projections (z = 0/1/2)
    dim3 gQKV(EMB / 128, MROWS / 128, 3);
    gemm_proj<<<gQKV, 256>>>(X, wq, bq, wk, bk, wv, bv, qp, kp, vtp, 1);

    dim3 gScores(T_LEN / 128, T_LEN / 128, BH);    // (16,16,64)
    gemm_scores<<<gScores, 256>>>();

    softmax_stats_avg<<<BSZ * T_LEN, 512, NH * T_LEN * (int)sizeof(float)>>>(avg);

    dim3 gCtx(T_LEN / 128, BH);                    // (16,64)
    gemm_ctx<<<gCtx, 256>>>();

    dim3 gOut(EMB / 128, MROWS / 128);
    gemm_proj<<<gOut, 256>>>(ctxp, wo, bo, nullptr, nullptr, nullptr, nullptr,
                             out, nullptr, nullptr, 0);
}

// round 5
// speedup vs baseline: 2.4454x; 1.0183x over previous
#include <cuda_runtime.h>
#include <cstdint>
#include <cstddef>

#define T_LEN 2048
#define BSZ   4
#define EMB   1024
#define NH    16
#define HDIM  64
#define MROWS (T_LEN * BSZ)   // 8192
#define BH    (BSZ * NH)      // 64
#define LDA   36              // padded row stride (u32) for 32-wide k tiles

// dynamic smem sizes (bytes)
#define SMEM_PROJ  (2 * 2 * 128 * LDA * 4)            // As[2] + Ws[2] = 73728
#define SMEM_CTX   ((2 * 128 + 2 * 64) * LDA * 4)     // As[2] + Vs[2] = 55296

// ---------------------------------------------------------------------------
// Scratch (device globals)
// ---------------------------------------------------------------------------
__device__ float g_q  [(size_t)BH * T_LEN * HDIM];   // [z][t][d]   (tf32-rounded)
__device__ float g_k  [(size_t)BH * T_LEN * HDIM];   // [z][t][d]   (tf32-rounded)
__device__ float g_vt [(size_t)BH * HDIM * T_LEN];   // [z][d][t]   (tf32-rounded)
__device__ float g_ctx[(size_t)MROWS * EMB];         // [t*B+b][e]  (tf32-rounded)
__device__ float g_S  [(size_t)BH * T_LEN * T_LEN];  // scores -> probs (in place)
__device__ float g_xt [(size_t)MROWS * EMB];         // X rounded to tf32
__device__ float g_wt [(size_t)4 * EMB * EMB];       // wq,wk,wv,wo rounded

// ---------------------------------------------------------------------------
// helpers
// ---------------------------------------------------------------------------
__device__ __forceinline__ uint32_t f2tf(float x) {
    uint32_t r; asm("cvt.rna.tf32.f32 %0, %1;" : "=r"(r) : "f"(x)); return r;
}
__device__ __forceinline__ float f2tff(float x) { return __uint_as_float(f2tf(x)); }

__device__ __forceinline__ void mma8(float* d, const uint32_t* a, const uint32_t* b) {
    asm volatile(
        "mma.sync.aligned.m16n8k8.row.col.f32.tf32.tf32.f32 "
        "{%0,%1,%2,%3}, {%4,%5,%6,%7}, {%8,%9}, {%0,%1,%2,%3};"
        : "+f"(d[0]), "+f"(d[1]), "+f"(d[2]), "+f"(d[3])
        : "r"(a[0]), "r"(a[1]), "r"(a[2]), "r"(a[3]), "r"(b[0]), "r"(b[1]));
}
__device__ __forceinline__ uint32_t sptr(const void* p) {
    return (uint32_t)__cvta_generic_to_shared(p);
}
__device__ __forceinline__ void ldsm4(uint32_t* r, uint32_t addr) {
    asm volatile("ldmatrix.sync.aligned.m8n8.x4.shared.b16 {%0,%1,%2,%3}, [%4];"
                 : "=r"(r[0]), "=r"(r[1]), "=r"(r[2]), "=r"(r[3]) : "r"(addr));
}
__device__ __forceinline__ void cpa16(uint32_t s, const void* g) {
    asm volatile("cp.async.cg.shared.global [%0], [%1], 16;" :: "r"(s), "l"(g));
}
__device__ __forceinline__ void cp_commit() {
    asm volatile("cp.async.commit_group;");
}
__device__ __forceinline__ void cp_wait1() {
    asm volatile("cp.async.wait_group 1;");
}

// ---------------------------------------------------------------------------
// tf32 pre-round kernel (grid-stride over float4)
// ---------------------------------------------------------------------------
__global__ void round_tf32(const float4* __restrict__ src, float4* __restrict__ dst, int n4)
{
    int i = blockIdx.x * blockDim.x + threadIdx.x;
    if (i < n4) {
        float4 v = src[i];
        dst[i] = make_float4(f2tff(v.x), f2tff(v.y), f2tff(v.z), f2tff(v.w));
    }
}

// ---------------------------------------------------------------------------
// Projection GEMM: C = (A[M,K] @ W[N,K]^T + bias) * scale, K=1024.
// Operands pre-rounded tf32 bits -> cp.async double-buffered (dynamic smem).
// BM=BN=128, BK=32, 256 thr, warps 2(m) x 4(n), warp tile 64x32.
// ---------------------------------------------------------------------------
__global__ __launch_bounds__(256) void gemm_proj(
    const float* __restrict__ A,
    const float* __restrict__ W0, const float* __restrict__ b0_,
    const float* __restrict__ W1, const float* __restrict__ b1_,
    const float* __restrict__ W2, const float* __restrict__ b2_,
    float* __restrict__ C0, float* __restrict__ C1, float* __restrict__ C2,
    int qkv)
{
    extern __shared__ __align__(16) uint32_t smem[];
    uint32_t* As = smem;                    // [2][128*LDA]
    uint32_t* Ws = smem + 2 * 128 * LDA;    // [2][128*LDA]

    const float* W; const float* bias; float* C; float scale; int mode;
    if (qkv) {
        if (blockIdx.z == 0)      { W = W0; bias = b0_; C = C0; scale = 0.125f; mode = 0; }
        else if (blockIdx.z == 1) { W = W1; bias = b1_; C = C1; scale = 1.0f;   mode = 0; }
        else                      { W = W2; bias = b2_; C = C2; scale = 1.0f;   mode = 2; }
    } else { W = W0; bias = b0_; C = C0; scale = 1.0f; mode = 3; }

    const int tid  = threadIdx.x;
    const int warp = tid >> 5, lane = tid & 31;
    const int g    = lane >> 2, tg = lane & 3;
    const int wm   = warp >> 2, wn = warp & 3;     // 2 x 4
    const int m0   = blockIdx.y * 128;
    const int n0   = blockIdx.x * 128;
    const int lr   = tid >> 1;
    const int lc   = (tid & 1) * 16;

    const int a_row = wm * 64 + (lane & 15);
    const int a_col = (lane >> 4) * 4;
    const int b_row = wn * 32 + ((lane >> 4) * 8) + (lane & 7);
    const int b_col = ((lane >> 3) & 1) * 4;

    const float* Ap = A + (size_t)(m0 + lr) * EMB + lc;
    const float* Wp = W + (size_t)(n0 + lr) * EMB + lc;
    const uint32_t sa0 = sptr(&As[lr * LDA + lc]);
    const uint32_t sw0 = sptr(&Ws[lr * LDA + lc]);
    const uint32_t bufB = (uint32_t)(128 * LDA * 4);

    float acc[4][4][4];
#pragma unroll
    for (int i = 0; i < 4; i++)
#pragma unroll
        for (int j = 0; j < 4; j++)
#pragma unroll
            for (int c = 0; c < 4; c++) acc[i][j][c] = 0.0f;

#pragma unroll
    for (int s = 0; s < 2; s++) {
#pragma unroll
        for (int v = 0; v < 4; v++) {
            cpa16(sa0 + s * bufB + v * 16, Ap + s * 32 + v * 4);
            cpa16(sw0 + s * bufB + v * 16, Wp + s * 32 + v * 4);
        }
        cp_commit();
    }

    const int NIT = EMB / 32;
    for (int it = 0; it < NIT; ++it) {
        cp_wait1();
        __syncthreads();
        const int cur = it & 1;
        const uint32_t sA = sptr(As) + cur * bufB;
        const uint32_t sW = sptr(Ws) + cur * bufB;
#pragma unroll
        for (int kk = 0; kk < 32; kk += 8) {
            uint32_t af[4][4], bf[4][2];
#pragma unroll
            for (int mb = 0; mb < 4; mb++)
                ldsm4(af[mb], sA + (((a_row + mb * 16) * LDA) + kk + a_col) * 4u);
#pragma unroll
            for (int p = 0; p < 2; p++) {
                uint32_t t[4];
                ldsm4(t, sW + (((b_row + p * 16) * LDA) + kk + b_col) * 4u);
                bf[2 * p][0] = t[0]; bf[2 * p][1] = t[1];
                bf[2 * p + 1][0] = t[2]; bf[2 * p + 1][1] = t[3];
            }
#pragma unroll
            for (int mb = 0; mb < 4; mb++)
#pragma unroll
                for (int nb = 0; nb < 4; nb++)
                    mma8(acc[mb][nb], af[mb], bf[nb]);
        }
        __syncthreads();
        if (it + 2 < NIT) {
            const int k0 = (it + 2) * 32;
#pragma unroll
            for (int v = 0; v < 4; v++) {
                cpa16(sa0 + cur * bufB + v * 16, Ap + k0 + v * 4);
                cpa16(sw0 + cur * bufB + v * 16, Wp + k0 + v * 4);
            }
        }
        cp_commit();
    }

#pragma unroll
    for (int mb = 0; mb < 4; mb++) {
#pragma unroll
        for (int nb = 0; nb < 4; nb++) {
            const int n = n0 + wn * 32 + nb * 8 + tg * 2;
            const float bb0 = bias[n], bb1 = bias[n + 1];
#pragma unroll
            for (int half = 0; half < 2; half++) {
                const int m = m0 + wm * 64 + mb * 16 + g + half * 8;
                float v0 = (acc[mb][nb][half * 2 + 0] + bb0) * scale;
                float v1 = (acc[mb][nb][half * 2 + 1] + bb1) * scale;
                const int t = m >> 2;       // m / BSZ
                const int b = m & 3;        // m % BSZ
                if (mode == 0) {
                    const int h = n >> 6, d = n & 63;
                    float* dst = C + (((size_t)b * NH + h) * T_LEN + t) * HDIM + d;
                    dst[0] = f2tff(v0); dst[1] = f2tff(v1);
                } else if (mode == 2) {
                    const int h = n >> 6, d = n & 63;
                    float* dst = C + (((size_t)b * NH + h) * HDIM + d) * T_LEN + t;
                    dst[0] = f2tff(v0); dst[T_LEN] = f2tff(v1);
                } else {
                    float* dst = C + (size_t)m * EMB + n;
                    dst[0] = v0; dst[1] = v1;
                }
            }
        }
    }
}

// ---------------------------------------------------------------------------
// Scores GEMM: S[z,q,k] = q[z,q,:] . k[z,k,:],  K = 64 (2 pipeline stages)
// ---------------------------------------------------------------------------
__global__ __launch_bounds__(256) void gemm_scores()
{
    extern __shared__ __align__(16) uint32_t smem[];
    uint32_t* As = smem;
    uint32_t* Bs = smem + 2 * 128 * LDA;

    const int z    = blockIdx.z;
    const float* A = g_q + (size_t)z * T_LEN * HDIM;
    const float* B = g_k + (size_t)z * T_LEN * HDIM;
    float*      Co = g_S + (size_t)z * T_LEN * T_LEN;

    const int tid  = threadIdx.x;
    const int warp = tid >> 5, lane = tid & 31;
    const int g    = lane >> 2, tg = lane & 3;
    const int wm   = warp >> 2, wn = warp & 3;
    const int m0   = blockIdx.y * 128;
    const int n0   = blockIdx.x * 128;
    const int lr   = tid >> 1;
    const int lc   = (tid & 1) * 16;

    const int a_row = wm * 64 + (lane & 15);
    const int a_col = (lane >> 4) * 4;
    const int b_row = wn * 32 + ((lane >> 4) * 8) + (lane & 7);
    const int b_col = ((lane >> 3) & 1) * 4;

    const float* Ap = A + (size_t)(m0 + lr) * HDIM + lc;
    const float* Bp = B + (size_t)(n0 + lr) * HDIM + lc;
    const uint32_t sa0 = sptr(&As[lr * LDA + lc]);
    const uint32_t sb0 = sptr(&Bs[lr * LDA + lc]);
    const uint32_t bufB = (uint32_t)(128 * LDA * 4);

    float acc[4][4][4];
#pragma unroll
    for (int i = 0; i < 4; i++)
#pragma unroll
        for (int j = 0; j < 4; j++)
#pragma unroll
            for (int c = 0; c < 4; c++) acc[i][j][c] = 0.0f;

#pragma unroll
    for (int s = 0; s < 2; s++) {
#pragma unroll
        for (int v = 0; v < 4; v++) {
            cpa16(sa0 + s * bufB + v * 16, Ap + s * 32 + v * 4);
            cpa16(sb0 + s * bufB + v * 16, Bp + s * 32 + v * 4);
        }
        cp_commit();
    }

#pragma unroll
    for (int it = 0; it < 2; ++it) {
        cp_wait1();
        __syncthreads();
        const uint32_t sA = sptr(As) + it * bufB;
        const uint32_t sB = sptr(Bs) + it * bufB;
#pragma unroll
        for (int kk = 0; kk < 32; kk += 8) {
            uint32_t af[4][4], bf[4][2];
#pragma unroll
            for (int mb = 0; mb < 4; mb++)
                ldsm4(af[mb], sA + (((a_row + mb * 16) * LDA) + kk + a_col) * 4u);
#pragma unroll
            for (int p = 0; p < 2; p++) {
                uint32_t t[4];
                ldsm4(t, sB + (((b_row + p * 16) * LDA) + kk + b_col) * 4u);
                bf[2 * p][0] = t[0]; bf[2 * p][1] = t[1];
                bf[2 * p + 1][0] = t[2]; bf[2 * p + 1][1] = t[3];
            }
#pragma unroll
            for (int mb = 0; mb < 4; mb++)
#pragma unroll
                for (int nb = 0; nb < 4; nb++)
                    mma8(acc[mb][nb], af[mb], bf[nb]);
        }
        __syncthreads();
        cp_commit();
    }

#pragma unroll
    for (int mb = 0; mb < 4; mb++)
#pragma unroll
        for (int nb = 0; nb < 4; nb++) {
            const int n = n0 + wn * 32 + nb * 8 + tg * 2;
#pragma unroll
            for (int half = 0; half < 2; half++) {
                const size_t m = m0 + wm * 64 + mb * 16 + g + half * 8;
                float* dst = Co + m * T_LEN + n;
                dst[0] = acc[mb][nb][half * 2 + 0];
                dst[1] = acc[mb][nb][half * 2 + 1];
            }
        }
}

// ---------------------------------------------------------------------------
// Softmax + head-average; writes tf32-rounded probs back into g_S in place.
// One CTA per (b,q), 16 warps = 16 heads. float4 I/O.
// ---------------------------------------------------------------------------
__global__ __launch_bounds__(512) void softmax_avg(float* __restrict__ avg_out)
{
    extern __shared__ float buf[];   // [NH][T_LEN]
    const int bq   = blockIdx.x;
    const int b    = bq / T_LEN;
    const int q    = bq % T_LEN;
    const int w    = threadIdx.x >> 5;
    const int lane = threadIdx.x & 31;

    float4* mybuf4 = (float4*)(buf + (size_t)w * T_LEN);
    float4* row4   = (float4*)(g_S + (((size_t)b * NH + w) * T_LEN + q) * T_LEN);

    float4 vals[16];
    float mx = -1e30f;
#pragma unroll
    for (int j = 0; j < 16; j++) {
        float4 v = row4[j * 32 + lane];
        vals[j] = v;
        mx = fmaxf(mx, fmaxf(fmaxf(v.x, v.y), fmaxf(v.z, v.w)));
    }
#pragma unroll
    for (int o = 16; o > 0; o >>= 1)
        mx = fmaxf(mx, __shfl_xor_sync(0xffffffffu, mx, o));

    float s = 0.0f;
#pragma unroll
    for (int j = 0; j < 16; j++) {
        float4 v = vals[j];
        v.x = __expf(v.x - mx); v.y = __expf(v.y - mx);
        v.z = __expf(v.z - mx); v.w = __expf(v.w - mx);
        vals[j] = v;
        s += (v.x + v.y) + (v.z + v.w);
    }
#pragma unroll
    for (int o = 16; o > 0; o >>= 1)
        s += __shfl_xor_sync(0xffffffffu, s, o);
    const float inv = 1.0f / s;

#pragma unroll
    for (int j = 0; j < 16; j++) {
        float4 v = vals[j];
        float4 p = make_float4(f2tff(v.x * inv), f2tff(v.y * inv),
                               f2tff(v.z * inv), f2tff(v.w * inv));
        mybuf4[j * 32 + lane] = p;
        row4[j * 32 + lane]   = p;
    }
    __syncthreads();

    for (int idx = threadIdx.x; idx < T_LEN; idx += 512) {
        float a = 0.0f;
#pragma unroll
        for (int hh = 0; hh < NH; hh++)
            a += buf[(size_t)hh * T_LEN + idx];
        avg_out[((size_t)b * T_LEN + q) * T_LEN + idx] = a * (1.0f / NH);
    }
}

// ---------------------------------------------------------------------------
// Context GEMM (pure, pipelined): ctx[z,q,d] = sum_k P[z,q,k] * Vt[z,d,k]
// BM=128, BN=64, BK=32, warps 4(m) x 2(n), warp tile 32x32.
// ---------------------------------------------------------------------------
__global__ __launch_bounds__(256) void gemm_ctx()
{
    extern __shared__ __align__(16) uint32_t smem[];
    uint32_t* As = smem;                    // [2][128*LDA]
    uint32_t* Vs = smem + 2 * 128 * LDA;    // [2][64*LDA]

    const int z = blockIdx.y;
    const int b = z >> 4, h = z & 15;
    const float* Sp = g_S  + (size_t)z * T_LEN * T_LEN;
    const float* Vp = g_vt + (size_t)z * HDIM * T_LEN;

    const int tid  = threadIdx.x;
    const int warp = tid >> 5, lane = tid & 31;
    const int g    = lane >> 2, tg = lane & 3;
    const int wm   = warp >> 1, wn = warp & 1;   // 4 x 2
    const int m0   = blockIdx.x * 128;
    const int lr   = tid >> 1;
    const int lc   = (tid & 1) * 16;
    const int vr   = tid >> 2;           // 0..63
    const int vc   = (tid & 3) * 8;      // 0,8,16,24

    const int a_row = wm * 32 + (lane & 15);
    const int a_col = (lane >> 4) * 4;
    const int b_row = wn * 32 + ((lane >> 4) * 8) + (lane & 7);
    const int b_col = ((lane >> 3) & 1) * 4;

    const float* Ap = Sp + (size_t)(m0 + lr) * T_LEN + lc;
    const float* Bp = Vp + (size_t)vr * T_LEN + vc;
    const uint32_t sa0 = sptr(&As[lr * LDA + lc]);
    const uint32_t sv0 = sptr(&Vs[vr * LDA + vc]);
    const uint32_t abufB = (uint32_t)(128 * LDA * 4);
    const uint32_t vbufB = (uint32_t)(64 * LDA * 4);

    float acc[2][4][4];
#pragma unroll
    for (int i = 0; i < 2; i++)
#pragma unroll
        for (int j = 0; j < 4; j++)
#pragma unroll
            for (int c = 0; c < 4; c++) acc[i][j][c] = 0.0f;

#pragma unroll
    for (int s = 0; s < 2; s++) {
#pragma unroll
        for (int v = 0; v < 4; v++)
            cpa16(sa0 + s * abufB + v * 16, Ap + s * 32 + v * 4);
#pragma unroll
        for (int u = 0; u < 2; u++)
            cpa16(sv0 + s * vbufB + u * 16, Bp + s * 32 + u * 4);
        cp_commit();
    }

    const int NIT = T_LEN / 32;
    for (int it = 0; it < NIT; ++it) {
        cp_wait1();
        __syncthreads();
        const int cur = it & 1;
        const uint32_t sA = sptr(As) + cur * abufB;
        const uint32_t sV = sptr(Vs) + cur * vbufB;
#pragma unroll
        for (int kk = 0; kk < 32; kk += 8) {
            uint32_t af[2][4], bf[4][2];
#pragma unroll
            for (int mb = 0; mb < 2; mb++)
                ldsm4(af[mb], sA + (((a_row + mb * 16) * LDA) + kk + a_col) * 4u);
#pragma unroll
            for (int p = 0; p < 2; p++) {
                uint32_t t[4];
                ldsm4(t, sV + (((b_row + p * 16) * LDA) + kk + b_col) * 4u);
                bf[2 * p][0] = t[0]; bf[2 * p][1] = t[1];
                bf[2 * p + 1][0] = t[2]; bf[2 * p + 1][1] = t[3];
            }
#pragma unroll
            for (int mb = 0; mb < 2; mb++)
#pragma unroll
                for (int nb = 0; nb < 4; nb++)
                    mma8(acc[mb][nb], af[mb], bf[nb]);
        }
        __syncthreads();
        if (it + 2 < NIT) {
            const int k0 = (it + 2) * 32;
#pragma unroll
            for (int v = 0; v < 4; v++)
                cpa16(sa0 + cur * abufB + v * 16, Ap + k0 + v * 4);
#pragma unroll
            for (int u = 0; u < 2; u++)
                cpa16(sv0 + cur * vbufB + u * 16, Bp + k0 + u * 4);
        }
        cp_commit();
    }

#pragma unroll
    for (int mb = 0; mb < 2; mb++)
#pragma unroll
        for (int nb = 0; nb < 4; nb++) {
            const int d = wn * 32 + nb * 8 + tg * 2;
#pragma unroll
            for (int half = 0; half < 2; half++) {
                const int q = m0 + wm * 32 + mb * 16 + g + half * 8;
                float* dst = g_ctx + ((size_t)q * BSZ + b) * EMB + h * HDIM + d;
                dst[0] = f2tff(acc[mb][nb][half * 2 + 0]);
                dst[1] = f2tff(acc[mb][nb][half * 2 + 1]);
            }
        }
}

// ---------------------------------------------------------------------------
// Launch
// ---------------------------------------------------------------------------
extern "C" void kernel_launch(void* const* d_in, const int* in_sizes, int n_in,
                              void* d_out, int out_size)
{
    const float* X  = (const float*)d_in[0];
    const float* wq = (const float*)d_in[1];
    const float* bq = (const float*)d_in[2];
    const float* wk = (const float*)d_in[3];
    const float* bk = (const float*)d_in[4];
    const float* wv = (const float*)d_in[5];
    const float* bv = (const float*)d_in[6];
    const float* wo = (const float*)d_in[7];
    const float* bo = (const float*)d_in[8];

    float* out = (float*)d_out;                    // [T,B,E]
    float* avg = out + (size_t)T_LEN * BSZ * EMB;  // [B,Tq,Tk]

    float *qp, *kp, *vtp, *ctxp, *xtp, *wtp;
    cudaGetSymbolAddress((void**)&qp,   g_q);
    cudaGetSymbolAddress((void**)&kp,   g_k);
    cudaGetSymbolAddress((void**)&vtp,  g_vt);
    cudaGetSymbolAddress((void**)&ctxp, g_ctx);
    cudaGetSymbolAddress((void**)&xtp,  g_xt);
    cudaGetSymbolAddress((void**)&wtp,  g_wt);

    cudaFuncSetAttribute(gemm_proj,
                         cudaFuncAttributeMaxDynamicSharedMemorySize, SMEM_PROJ);
    cudaFuncSetAttribute(gemm_scores,
                         cudaFuncAttributeMaxDynamicSharedMemorySize, SMEM_PROJ);
    cudaFuncSetAttribute(gemm_ctx,
                         cudaFuncAttributeMaxDynamicSharedMemorySize, SMEM_CTX);
    cudaFuncSetAttribute(softmax_avg,
                         cudaFuncAttributeMaxDynamicSharedMemorySize,
                         NH * T_LEN * (int)sizeof(float));

    const size_t WSZ = (size_t)EMB * EMB;

    // pre-round operands to tf32
    {
        int n4 = (int)((size_t)MROWS * EMB / 4);
        round_tf32<<<(n4 + 255) / 256, 256>>>((const float4*)X, (float4*)xtp, n4);
        int w4 = (int)(WSZ / 4);
        round_tf32<<<(w4 + 255) / 256, 256>>>((const float4*)wq, (float4*)(wtp + 0 * WSZ), w4);
        round_tf32<<<(w4 + 255) / 256, 256>>>((const float4*)wk, (float4*)(wtp + 1 * WSZ), w4);
        round_tf32<<<(w4 + 255) / 256, 256>>>((const float4*)wv, (float4*)(wtp + 2 * WSZ), w4);
        round_tf32<<<(w4 + 255) / 256, 256>>>((const float4*)wo, (float4*)(wtp + 3 * WSZ), w4);
    }

    // fused q,k,v projections (z = 0/1/2)
    dim3 gQKV(EMB / 128, MROWS / 128, 3);
    gemm_proj<<<gQKV, 256, SMEM_PROJ>>>(xtp, wtp + 0 * WSZ, bq, wtp + 1 * WSZ, bk,
                                        wtp + 2 * WSZ, bv, qp, kp, vtp, 1);

    dim3 gScores(T_LEN / 128, T_LEN / 128, BH);    // (16,16,64)
    gemm_scores<<<gScores, 256, SMEM_PROJ>>>();

    softmax_avg<<<BSZ * T_LEN, 512, NH * T_LEN * (int)sizeof(float)>>>(avg);

    dim3 gCtx(T_LEN / 128, BH);                    // (16,64)
    gemm_ctx<<<gCtx, 256, SMEM_CTX>>>();

    dim3 gOut(EMB / 128, MROWS / 128);
    gemm_proj<<<gOut, 256, SMEM_PROJ>>>(ctxp, wtp + 3 * WSZ, bo, nullptr, nullptr,
                                        nullptr, nullptr, out, nullptr, nullptr, 0);
}

// round 7
// speedup vs baseline: 2.5559x; 1.0452x over previous
#include <cuda_runtime.h>
#include <cstdint>
#include <cstddef>

#define T_LEN 2048
#define BSZ   4
#define EMB   1024
#define NH    16
#define HDIM  64
#define MROWS (T_LEN * BSZ)   // 8192
#define BH    (BSZ * NH)      // 64
#define LDA   36              // padded row stride (u32) for 32-wide k tiles
#define LDT   68              // padded row stride (u32) for 64-wide tiles

// dynamic smem sizes (bytes)
#define SMEM_PROJ (2 * 2 * 128 * LDA * 4)                 // 73728
#define SMEM_ATT  ((128 * LDT + 4 * 64 * LDT) * 4)        // Pq + K0K1V0V1 = 104448
#define SMEM_AVG  ((2 * 128 * LDT + 2 * 64 * LDT) * 4)    // q0q1 + k0k1   = 104448

// ---------------------------------------------------------------------------
// Scratch (device globals)
// ---------------------------------------------------------------------------
__device__ float g_q  [(size_t)BH * T_LEN * HDIM];   // [z][t][d]  (tf32-rounded)
__device__ float g_k  [(size_t)BH * T_LEN * HDIM];   // [z][t][d]  (tf32-rounded)
__device__ float g_vt [(size_t)BH * HDIM * T_LEN];   // [z][d][t]  (tf32-rounded)
__device__ float g_ctx[(size_t)MROWS * EMB];         // [t*B+b][e] (tf32-rounded)
__device__ float g_rm [(size_t)BH * T_LEN];          // final row max
__device__ float g_rz [(size_t)BH * T_LEN];          // final 1/rowsum
__device__ float g_xt [(size_t)MROWS * EMB];         // X rounded to tf32
__device__ float g_wt [(size_t)4 * EMB * EMB];       // wq,wk,wv,wo rounded

// ---------------------------------------------------------------------------
// helpers
// ---------------------------------------------------------------------------
__device__ __forceinline__ uint32_t f2tf(float x) {
    uint32_t r; asm("cvt.rna.tf32.f32 %0, %1;" : "=r"(r) : "f"(x)); return r;
}
__device__ __forceinline__ float f2tff(float x) { return __uint_as_float(f2tf(x)); }

__device__ __forceinline__ void mma8(float* d, const uint32_t* a, const uint32_t* b) {
    asm volatile(
        "mma.sync.aligned.m16n8k8.row.col.f32.tf32.tf32.f32 "
        "{%0,%1,%2,%3}, {%4,%5,%6,%7}, {%8,%9}, {%0,%1,%2,%3};"
        : "+f"(d[0]), "+f"(d[1]), "+f"(d[2]), "+f"(d[3])
        : "r"(a[0]), "r"(a[1]), "r"(a[2]), "r"(a[3]), "r"(b[0]), "r"(b[1]));
}
__device__ __forceinline__ uint32_t sptr(const void* p) {
    return (uint32_t)__cvta_generic_to_shared(p);
}
__device__ __forceinline__ void ldsm4(uint32_t* r, uint32_t addr) {
    asm volatile("ldmatrix.sync.aligned.m8n8.x4.shared.b16 {%0,%1,%2,%3}, [%4];"
                 : "=r"(r[0]), "=r"(r[1]), "=r"(r[2]), "=r"(r[3]) : "r"(addr));
}
__device__ __forceinline__ void cpa16(uint32_t s, const void* g) {
    asm volatile("cp.async.cg.shared.global [%0], [%1], 16;" :: "r"(s), "l"(g));
}
__device__ __forceinline__ void cp_commit() { asm volatile("cp.async.commit_group;"); }
__device__ __forceinline__ void cp_wait1()  { asm volatile("cp.async.wait_group 1;"); }

// ---------------------------------------------------------------------------
// tf32 pre-round kernel
// ---------------------------------------------------------------------------
__global__ void round_tf32(const float4* __restrict__ src, float4* __restrict__ dst, int n4)
{
    int i = blockIdx.x * blockDim.x + threadIdx.x;
    if (i < n4) {
        float4 v = src[i];
        dst[i] = make_float4(f2tff(v.x), f2tff(v.y), f2tff(v.z), f2tff(v.w));
    }
}

// ---------------------------------------------------------------------------
// Projection GEMM (unchanged from R5): C = (A @ W^T + bias) * scale, K=1024
// ---------------------------------------------------------------------------
__global__ __launch_bounds__(256) void gemm_proj(
    const float* __restrict__ A,
    const float* __restrict__ W0, const float* __restrict__ b0_,
    const float* __restrict__ W1, const float* __restrict__ b1_,
    const float* __restrict__ W2, const float* __restrict__ b2_,
    float* __restrict__ C0, float* __restrict__ C1, float* __restrict__ C2,
    int qkv)
{
    extern __shared__ __align__(16) uint32_t smem[];
    uint32_t* As = smem;
    uint32_t* Ws = smem + 2 * 128 * LDA;

    const float* W; const float* bias; float* C; float scale; int mode;
    if (qkv) {
        if (blockIdx.z == 0)      { W = W0; bias = b0_; C = C0; scale = 0.125f; mode = 0; }
        else if (blockIdx.z == 1) { W = W1; bias = b1_; C = C1; scale = 1.0f;   mode = 0; }
        else                      { W = W2; bias = b2_; C = C2; scale = 1.0f;   mode = 2; }
    } else { W = W0; bias = b0_; C = C0; scale = 1.0f; mode = 3; }

    const int tid  = threadIdx.x;
    const int warp = tid >> 5, lane = tid & 31;
    const int g    = lane >> 2, tg = lane & 3;
    const int wm   = warp >> 2, wn = warp & 3;
    const int m0   = blockIdx.y * 128;
    const int n0   = blockIdx.x * 128;
    const int lr   = tid >> 1;
    const int lc   = (tid & 1) * 16;

    const int a_row = wm * 64 + (lane & 15);
    const int a_col = (lane >> 4) * 4;
    const int b_row = wn * 32 + ((lane >> 4) * 8) + (lane & 7);
    const int b_col = ((lane >> 3) & 1) * 4;

    const float* Ap = A + (size_t)(m0 + lr) * EMB + lc;
    const float* Wp = W + (size_t)(n0 + lr) * EMB + lc;
    const uint32_t sa0 = sptr(&As[lr * LDA + lc]);
    const uint32_t sw0 = sptr(&Ws[lr * LDA + lc]);
    const uint32_t bufB = (uint32_t)(128 * LDA * 4);

    float acc[4][4][4];
#pragma unroll
    for (int i = 0; i < 4; i++)
#pragma unroll
        for (int j = 0; j < 4; j++)
#pragma unroll
            for (int c = 0; c < 4; c++) acc[i][j][c] = 0.0f;

#pragma unroll
    for (int s = 0; s < 2; s++) {
#pragma unroll
        for (int v = 0; v < 4; v++) {
            cpa16(sa0 + s * bufB + v * 16, Ap + s * 32 + v * 4);
            cpa16(sw0 + s * bufB + v * 16, Wp + s * 32 + v * 4);
        }
        cp_commit();
    }

    const int NIT = EMB / 32;
    for (int it = 0; it < NIT; ++it) {
        cp_wait1();
        __syncthreads();
        const int cur = it & 1;
        const uint32_t sA = sptr(As) + cur * bufB;
        const uint32_t sW = sptr(Ws) + cur * bufB;
#pragma unroll
        for (int kk = 0; kk < 32; kk += 8) {
            uint32_t af[4][4], bf[4][2];
#pragma unroll
            for (int mb = 0; mb < 4; mb++)
                ldsm4(af[mb], sA + (((a_row + mb * 16) * LDA) + kk + a_col) * 4u);
#pragma unroll
            for (int p = 0; p < 2; p++) {
                uint32_t t[4];
                ldsm4(t, sW + (((b_row + p * 16) * LDA) + kk + b_col) * 4u);
                bf[2 * p][0] = t[0]; bf[2 * p][1] = t[1];
                bf[2 * p + 1][0] = t[2]; bf[2 * p + 1][1] = t[3];
            }
#pragma unroll
            for (int mb = 0; mb < 4; mb++)
#pragma unroll
                for (int nb = 0; nb < 4; nb++)
                    mma8(acc[mb][nb], af[mb], bf[nb]);
        }
        __syncthreads();
        if (it + 2 < NIT) {
            const int k0 = (it + 2) * 32;
#pragma unroll
            for (int v = 0; v < 4; v++) {
                cpa16(sa0 + cur * bufB + v * 16, Ap + k0 + v * 4);
                cpa16(sw0 + cur * bufB + v * 16, Wp + k0 + v * 4);
            }
        }
        cp_commit();
    }

#pragma unroll
    for (int mb = 0; mb < 4; mb++) {
#pragma unroll
        for (int nb = 0; nb < 4; nb++) {
            const int n = n0 + wn * 32 + nb * 8 + tg * 2;
            const float bb0 = bias[n], bb1 = bias[n + 1];
#pragma unroll
            for (int half = 0; half < 2; half++) {
                const int m = m0 + wm * 64 + mb * 16 + g + half * 8;
                float v0 = (acc[mb][nb][half * 2 + 0] + bb0) * scale;
                float v1 = (acc[mb][nb][half * 2 + 1] + bb1) * scale;
                const int t = m >> 2;
                const int b = m & 3;
                if (mode == 0) {
                    const int h = n >> 6, d = n & 63;
                    float* dst = C + (((size_t)b * NH + h) * T_LEN + t) * HDIM + d;
                    dst[0] = f2tff(v0); dst[1] = f2tff(v1);
                } else if (mode == 2) {
                    const int h = n >> 6, d = n & 63;
                    float* dst = C + (((size_t)b * NH + h) * HDIM + d) * T_LEN + t;
                    dst[0] = f2tff(v0); dst[T_LEN] = f2tff(v1);
                } else {
                    float* dst = C + (size_t)m * EMB + n;
                    dst[0] = v0; dst[1] = v1;
                }
            }
        }
    }
}

// ---------------------------------------------------------------------------
// Fused attention: one CTA per (z, 128-row q tile). Online softmax; never
// materializes S. Writes ctx (tf32-rounded) + per-row (max, 1/sum).
// ---------------------------------------------------------------------------
__global__ __launch_bounds__(256) void attn_fused()
{
    extern __shared__ __align__(16) uint32_t smem[];
    uint32_t* Pq = smem;                            // [128*LDT] q staging, then P
    uint32_t* Kt = smem + 128 * LDT;                // [2][64*LDT]
    uint32_t* Vt = smem + 128 * LDT + 2 * 64 * LDT; // [2][64*LDT]

    const int z  = blockIdx.y;
    const int b  = z >> 4, h = z & 15;
    const int q0 = blockIdx.x * 128;

    const float* Qp = g_q  + (size_t)z * T_LEN * HDIM;
    const float* Kp = g_k  + (size_t)z * T_LEN * HDIM;
    const float* Vp = g_vt + (size_t)z * HDIM * T_LEN;

    const int tid  = threadIdx.x;
    const int warp = tid >> 5, lane = tid & 31;
    const int g    = lane >> 2, tg = lane & 3;

    // stage q tile into Pq (one-time)
    {
        const int row = tid >> 1;
        const int cw  = (tid & 1) * 32;
        const float* src = Qp + (size_t)(q0 + row) * HDIM + cw;
        uint32_t* dst = Pq + row * LDT + cw;
#pragma unroll
        for (int i = 0; i < 8; i++)
            *(float4*)(dst + i * 4) = *(const float4*)(src + i * 4);
    }
    __syncthreads();

    // q fragments held in registers for entire kernel
    uint32_t aq[8][4];
    {
        const uint32_t base = sptr(Pq) + ((warp * 16 + (lane & 15)) * LDT + (lane >> 4) * 4) * 4u;
#pragma unroll
        for (int kk = 0; kk < 8; kk++)
            ldsm4(aq[kk], base + (uint32_t)(kk * 8) * 4u);
    }

    // prefetch KV tiles 0,1 — FULL rows: 4 threads/row x 4 cpa16 = 256B/row
    const int krow = tid >> 2, kcw = (tid & 3) * 16;   // u32 col base
    const uint32_t sK0 = sptr(Kt) + (krow * LDT + kcw) * 4u;
    const uint32_t sV0 = sptr(Vt) + (krow * LDT + kcw) * 4u;
    const uint32_t kbufB = (uint32_t)(64 * LDT * 4);
#pragma unroll
    for (int s = 0; s < 2; s++) {
#pragma unroll
        for (int v = 0; v < 4; v++) {
            cpa16(sK0 + s * kbufB + v * 16, Kp + (size_t)(s * 64 + krow) * HDIM + kcw + v * 4);
            cpa16(sV0 + s * kbufB + v * 16, Vp + (size_t)krow * T_LEN + s * 64 + kcw + v * 4);
        }
        cp_commit();
    }

    float cacc[8][4];
#pragma unroll
    for (int nb = 0; nb < 8; nb++)
#pragma unroll
        for (int c = 0; c < 4; c++) cacc[nb][c] = 0.0f;
    float m0 = -1e30f, m1 = -1e30f, l0 = 0.0f, l1 = 0.0f;

    const uint32_t sKb = sptr(Kt), sVb = sptr(Vt), sP = sptr(Pq);
    const int nrow = ((lane >> 4) * 8) + (lane & 7);
    const int ncol = ((lane >> 3) & 1) * 4;
    const int arow = warp * 16 + (lane & 15);
    const int acol = (lane >> 4) * 4;

    const int NT = T_LEN / 64;   // 32
    for (int it = 0; it < NT; ++it) {
        cp_wait1();
        __syncthreads();
        const uint32_t sK = sKb + (it & 1) * kbufB;
        const uint32_t sV = sVb + (it & 1) * kbufB;

        // ---- S = q . k^T (m16 x n64 x k64) ----
        float sacc[8][4];
#pragma unroll
        for (int nb = 0; nb < 8; nb++)
#pragma unroll
            for (int c = 0; c < 4; c++) sacc[nb][c] = 0.0f;
#pragma unroll
        for (int kk = 0; kk < 8; kk++) {
#pragma unroll
            for (int p = 0; p < 4; p++) {
                uint32_t t[4];
                ldsm4(t, sK + ((p * 16 + nrow) * LDT + kk * 8 + ncol) * 4u);
                mma8(sacc[2 * p],     aq[kk], t);
                mma8(sacc[2 * p + 1], aq[kk], t + 2);
            }
        }

        // ---- online softmax ----
        float tm0 = m0, tm1 = m1;
#pragma unroll
        for (int nb = 0; nb < 8; nb++) {
            tm0 = fmaxf(tm0, fmaxf(sacc[nb][0], sacc[nb][1]));
            tm1 = fmaxf(tm1, fmaxf(sacc[nb][2], sacc[nb][3]));
        }
        tm0 = fmaxf(tm0, __shfl_xor_sync(0xffffffffu, tm0, 1));
        tm0 = fmaxf(tm0, __shfl_xor_sync(0xffffffffu, tm0, 2));
        tm1 = fmaxf(tm1, __shfl_xor_sync(0xffffffffu, tm1, 1));
        tm1 = fmaxf(tm1, __shfl_xor_sync(0xffffffffu, tm1, 2));
        const float sc0 = __expf(m0 - tm0), sc1 = __expf(m1 - tm1);
        m0 = tm0; m1 = tm1;

        float rs0 = 0.0f, rs1 = 0.0f;
#pragma unroll
        for (int nb = 0; nb < 8; nb++) {
            sacc[nb][0] = __expf(sacc[nb][0] - m0);
            sacc[nb][1] = __expf(sacc[nb][1] - m0);
            sacc[nb][2] = __expf(sacc[nb][2] - m1);
            sacc[nb][3] = __expf(sacc[nb][3] - m1);
            rs0 += sacc[nb][0] + sacc[nb][1];
            rs1 += sacc[nb][2] + sacc[nb][3];
        }
        rs0 += __shfl_xor_sync(0xffffffffu, rs0, 1);
        rs0 += __shfl_xor_sync(0xffffffffu, rs0, 2);
        rs1 += __shfl_xor_sync(0xffffffffu, rs1, 1);
        rs1 += __shfl_xor_sync(0xffffffffu, rs1, 2);
        l0 = l0 * sc0 + rs0;
        l1 = l1 * sc1 + rs1;
#pragma unroll
        for (int nb = 0; nb < 8; nb++) {
            cacc[nb][0] *= sc0; cacc[nb][1] *= sc0;
            cacc[nb][2] *= sc1; cacc[nb][3] *= sc1;
        }

        // ---- store P (tf32) to warp-private smem rows ----
#pragma unroll
        for (int nb = 0; nb < 8; nb++) {
            uint32_t* p0 = Pq + (warp * 16 + g) * LDT + nb * 8 + tg * 2;
            p0[0] = f2tf(sacc[nb][0]); p0[1] = f2tf(sacc[nb][1]);
            uint32_t* p1 = Pq + (warp * 16 + g + 8) * LDT + nb * 8 + tg * 2;
            p1[0] = f2tf(sacc[nb][2]); p1[1] = f2tf(sacc[nb][3]);
        }
        __syncwarp();

        // ---- ctx += P . Vt (m16 x n64(d) x k64(kv)) ----
#pragma unroll
        for (int kk = 0; kk < 8; kk++) {
            uint32_t ap[4];
            ldsm4(ap, sP + (arow * LDT + kk * 8 + acol) * 4u);
#pragma unroll
            for (int p = 0; p < 4; p++) {
                uint32_t t[4];
                ldsm4(t, sV + ((p * 16 + nrow) * LDT + kk * 8 + ncol) * 4u);
                mma8(cacc[2 * p],     ap, t);
                mma8(cacc[2 * p + 1], ap, t + 2);
            }
        }
        __syncthreads();

        if (it + 2 < NT) {
#pragma unroll
            for (int v = 0; v < 4; v++) {
                cpa16(sK0 + (it & 1) * kbufB + v * 16,
                      Kp + (size_t)((it + 2) * 64 + krow) * HDIM + kcw + v * 4);
                cpa16(sV0 + (it & 1) * kbufB + v * 16,
                      Vp + (size_t)krow * T_LEN + (it + 2) * 64 + kcw + v * 4);
            }
        }
        cp_commit();
    }

    // ---- epilogue ----
    const float inv0 = 1.0f / l0, inv1 = 1.0f / l1;
    const int qr = q0 + warp * 16 + g;
#pragma unroll
    for (int nb = 0; nb < 8; nb++) {
        const int d = nb * 8 + tg * 2;
        float* d0 = g_ctx + ((size_t)qr * BSZ + b) * EMB + h * HDIM + d;
        d0[0] = f2tff(cacc[nb][0] * inv0);
        d0[1] = f2tff(cacc[nb][1] * inv0);
        float* d1 = g_ctx + ((size_t)(qr + 8) * BSZ + b) * EMB + h * HDIM + d;
        d1[0] = f2tff(cacc[nb][2] * inv1);
        d1[1] = f2tff(cacc[nb][3] * inv1);
    }
    if (tg == 0) {
        g_rm[(size_t)z * T_LEN + qr]     = m0;
        g_rz[(size_t)z * T_LEN + qr]     = inv0;
        g_rm[(size_t)z * T_LEN + qr + 8] = m1;
        g_rz[(size_t)z * T_LEN + qr + 8] = inv1;
    }
}

// ---------------------------------------------------------------------------
// Head-averaged attention weights: recompute S per head, apply exp with saved
// stats, average over heads. CTA = (b, 128-q tile, 64-k tile).
// ---------------------------------------------------------------------------
__global__ __launch_bounds__(256) void attn_avg(float* __restrict__ avg_out)
{
    extern __shared__ __align__(16) uint32_t smem[];
    uint32_t* Qs = smem;                   // [2][128*LDT]
    uint32_t* Ks = smem + 2 * 128 * LDT;   // [2][64*LDT]

    const int b  = blockIdx.z;
    const int q0 = blockIdx.y * 128;
    const int k0 = blockIdx.x * 64;

    const int tid  = threadIdx.x;
    const int warp = tid >> 5, lane = tid & 31;
    const int g    = lane >> 2, tg = lane & 3;

    // chunk maps — FULL rows
    const int qrow = tid >> 1, qc = (tid & 1) * 32;    // 2 thr/row x 8 cpa16
    const int krow = tid >> 2, kcw = (tid & 3) * 16;   // 4 thr/row x 4 cpa16

    const uint32_t qbufB = (uint32_t)(128 * LDT * 4);
    const uint32_t kbufB = (uint32_t)(64 * LDT * 4);
    const uint32_t sQ0 = sptr(Qs) + (qrow * LDT + qc) * 4u;
    const uint32_t sK0 = sptr(Ks) + (krow * LDT + kcw) * 4u;

#pragma unroll
    for (int s = 0; s < 2; s++) {
        const size_t zb = ((size_t)(b * NH + s)) * T_LEN * HDIM;
#pragma unroll
        for (int v = 0; v < 8; v++)
            cpa16(sQ0 + s * qbufB + v * 16, g_q + zb + (size_t)(q0 + qrow) * HDIM + qc + v * 4);
#pragma unroll
        for (int v = 0; v < 4; v++)
            cpa16(sK0 + s * kbufB + v * 16, g_k + zb + (size_t)(k0 + krow) * HDIM + kcw + v * 4);
        cp_commit();
    }

    const int nrow = ((lane >> 4) * 8) + (lane & 7);
    const int ncol = ((lane >> 3) & 1) * 4;
    const int arow = warp * 16 + (lane & 15);
    const int acol = (lane >> 4) * 4;
    const int qr   = q0 + warp * 16 + g;

    float sum[8][4];
#pragma unroll
    for (int nb = 0; nb < 8; nb++)
#pragma unroll
        for (int c = 0; c < 4; c++) sum[nb][c] = 0.0f;

    for (int h = 0; h < NH; ++h) {
        cp_wait1();
        __syncthreads();
        const int cur = h & 1;
        const uint32_t sQ = sptr(Qs) + cur * qbufB;
        const uint32_t sK = sptr(Ks) + cur * kbufB;

        float sacc[8][4];
#pragma unroll
        for (int nb = 0; nb < 8; nb++)
#pragma unroll
            for (int c = 0; c < 4; c++) sacc[nb][c] = 0.0f;
#pragma unroll
        for (int kk = 0; kk < 8; kk++) {
            uint32_t aq[4];
            ldsm4(aq, sQ + (arow * LDT + kk * 8 + acol) * 4u);
#pragma unroll
            for (int p = 0; p < 4; p++) {
                uint32_t t[4];
                ldsm4(t, sK + ((p * 16 + nrow) * LDT + kk * 8 + ncol) * 4u);
                mma8(sacc[2 * p],     aq, t);
                mma8(sacc[2 * p + 1], aq, t + 2);
            }
        }

        const size_t zq = ((size_t)(b * NH + h)) * T_LEN;
        const float mr0 = g_rm[zq + qr],     iz0 = g_rz[zq + qr];
        const float mr1 = g_rm[zq + qr + 8], iz1 = g_rz[zq + qr + 8];
#pragma unroll
        for (int nb = 0; nb < 8; nb++) {
            sum[nb][0] += __expf(sacc[nb][0] - mr0) * iz0;
            sum[nb][1] += __expf(sacc[nb][1] - mr0) * iz0;
            sum[nb][2] += __expf(sacc[nb][2] - mr1) * iz1;
            sum[nb][3] += __expf(sacc[nb][3] - mr1) * iz1;
        }
        __syncthreads();

        if (h + 2 < NH) {
            const size_t zb = ((size_t)(b * NH + h + 2)) * T_LEN * HDIM;
#pragma unroll
            for (int v = 0; v < 8; v++)
                cpa16(sQ0 + cur * qbufB + v * 16,
                      g_q + zb + (size_t)(q0 + qrow) * HDIM + qc + v * 4);
#pragma unroll
            for (int v = 0; v < 4; v++)
                cpa16(sK0 + cur * kbufB + v * 16,
                      g_k + zb + (size_t)(k0 + krow) * HDIM + kcw + v * 4);
        }
        cp_commit();
    }

    const float invH = 1.0f / NH;
#pragma unroll
    for (int nb = 0; nb < 8; nb++) {
        const int kc = k0 + nb * 8 + tg * 2;
        float* d0 = avg_out + ((size_t)b * T_LEN + qr) * T_LEN + kc;
        d0[0] = sum[nb][0] * invH; d0[1] = sum[nb][1] * invH;
        float* d1 = avg_out + ((size_t)b * T_LEN + qr + 8) * T_LEN + kc;
        d1[0] = sum[nb][2] * invH; d1[1] = sum[nb][3] * invH;
    }
}

// ---------------------------------------------------------------------------
// Launch
// ---------------------------------------------------------------------------
extern "C" void kernel_launch(void* const* d_in, const int* in_sizes, int n_in,
                              void* d_out, int out_size)
{
    const float* X  = (const float*)d_in[0];
    const float* wq = (const float*)d_in[1];
    const float* bq = (const float*)d_in[2];
    const float* wk = (const float*)d_in[3];
    const float* bk = (const float*)d_in[4];
    const float* wv = (const float*)d_in[5];
    const float* bv = (const float*)d_in[6];
    const float* wo = (const float*)d_in[7];
    const float* bo = (const float*)d_in[8];

    float* out = (float*)d_out;                    // [T,B,E]
    float* avg = out + (size_t)T_LEN * BSZ * EMB;  // [B,Tq,Tk]

    float *qp, *kp, *vtp, *ctxp, *xtp, *wtp;
    cudaGetSymbolAddress((void**)&qp,   g_q);
    cudaGetSymbolAddress((void**)&kp,   g_k);
    cudaGetSymbolAddress((void**)&vtp,  g_vt);
    cudaGetSymbolAddress((void**)&ctxp, g_ctx);
    cudaGetSymbolAddress((void**)&xtp,  g_xt);
    cudaGetSymbolAddress((void**)&wtp,  g_wt);

    cudaFuncSetAttribute(gemm_proj,
                         cudaFuncAttributeMaxDynamicSharedMemorySize, SMEM_PROJ);
    cudaFuncSetAttribute(attn_fused,
                         cudaFuncAttributeMaxDynamicSharedMemorySize, SMEM_ATT);
    cudaFuncSetAttribute(attn_avg,
                         cudaFuncAttributeMaxDynamicSharedMemorySize, SMEM_AVG);

    const size_t WSZ = (size_t)EMB * EMB;

    // pre-round operands to tf32
    {
        int n4 = (int)((size_t)MROWS * EMB / 4);
        round_tf32<<<(n4 + 255) / 256, 256>>>((const float4*)X, (float4*)xtp, n4);
        int w4 = (int)(WSZ / 4);
        round_tf32<<<(w4 + 255) / 256, 256>>>((const float4*)wq, (float4*)(wtp + 0 * WSZ), w4);
        round_tf32<<<(w4 + 255) / 256, 256>>>((const float4*)wk, (float4*)(wtp + 1 * WSZ), w4);
        round_tf32<<<(w4 + 255) / 256, 256>>>((const float4*)wv, (float4*)(wtp + 2 * WSZ), w4);
        round_tf32<<<(w4 + 255) / 256, 256>>>((const float4*)wo, (float4*)(wtp + 3 * WSZ), w4);
    }

    // fused q,k,v projections
    dim3 gQKV(EMB / 128, MROWS / 128, 3);
    gemm_proj<<<gQKV, 256, SMEM_PROJ>>>(xtp, wtp + 0 * WSZ, bq, wtp + 1 * WSZ, bk,
                                        wtp + 2 * WSZ, bv, qp, kp, vtp, 1);

    // fused attention (ctx + stats)
    dim3 gAtt(T_LEN / 128, BH);                    // (16, 64)
    attn_fused<<<gAtt, 256, SMEM_ATT>>>();

    // head-averaged attention weights
    dim3 gAvg(T_LEN / 64, T_LEN / 128, BSZ);       // (32, 16, 4)
    attn_avg<<<gAvg, 256, SMEM_AVG>>>(avg);

    // output projection
    dim3 gOut(EMB / 128, MROWS / 128);
    gemm_proj<<<gOut, 256, SMEM_PROJ>>>(ctxp, wtp + 3 * WSZ, bo, nullptr, nullptr,
                                        nullptr, nullptr, out, nullptr, nullptr, 0);
}